// round 6
// baseline (speedup 1.0000x reference)
#include <cuda_runtime.h>
#include <cstdint>

#define N_NODES 50000
#define N_EDGES 800000
#define H 64

// ---------------- scratch (device globals; no allocations) ----------------
__device__ __align__(16) float g_x0 [N_NODES * H];
__device__ __align__(16) float g_x  [N_NODES * H];
__device__ __align__(16) float g_a  [N_NODES * H];
__device__ __align__(16) float g_b  [N_NODES * H];
__device__ __align__(16) float g_acc[N_NODES * H];
__device__ __align__(16) int g_deg[N_NODES];
__device__ int g_off[N_NODES + 1];
__device__ int g_cursor[N_NODES];
__device__ int g_csr[N_EDGES];

// silu(z) = 0.5*z*(1 + tanh(z/2)) -- single MUFU.TANH
__device__ __forceinline__ float silu_f(float z) {
    float t;
    asm("tanh.approx.f32 %0, %1;" : "=f"(t) : "f"(0.5f * z));
    return 0.5f * z * (1.0f + t);
}
__device__ __forceinline__ float4 silu4(float4 z) {
    return make_float4(silu_f(z.x), silu_f(z.y), silu_f(z.z), silu_f(z.w));
}
__device__ __forceinline__ float4 add4(float4 a, float4 b) {
    return make_float4(a.x + b.x, a.y + b.y, a.z + b.z, a.w + b.w);
}

// ============================ CSR construction =============================
__global__ void k_zero_deg() {
    int i = blockIdx.x * blockDim.x + threadIdx.x;
    if (i < N_NODES) g_deg[i] = 0;
}

// 8 edges/thread for MLP on the atomics
__global__ void k_hist(const int* __restrict__ ei) {
    int i = blockIdx.x * blockDim.x + threadIdx.x;
    if (i < N_EDGES / 8) {
        int4 v0 = ((const int4*)ei)[i * 2];
        int4 v1 = ((const int4*)ei)[i * 2 + 1];
        atomicAdd(&g_deg[v0.x], 1); atomicAdd(&g_deg[v0.y], 1);
        atomicAdd(&g_deg[v0.z], 1); atomicAdd(&g_deg[v0.w], 1);
        atomicAdd(&g_deg[v1.x], 1); atomicAdd(&g_deg[v1.y], 1);
        atomicAdd(&g_deg[v1.z], 1); atomicAdd(&g_deg[v1.w], 1);
    }
}

// single-block scan, 4 elements/thread
__global__ __launch_bounds__(1024) void k_scan() {
    __shared__ int wsum[32];
    __shared__ int s_carry;
    const int tid = threadIdx.x, lane = tid & 31, w = tid >> 5;
    if (tid == 0) { g_off[0] = 0; s_carry = 0; }
    __syncthreads();
    const int NI4 = N_NODES / 4;  // 12500
    for (int base = 0; base < NI4; base += 1024) {
        int i4 = base + tid;
        int4 v = make_int4(0, 0, 0, 0);
        if (i4 < NI4) v = ((const int4*)g_deg)[i4];
        int s0 = v.x, s1 = s0 + v.y, s2 = s1 + v.z, s3 = s2 + v.w;
        int x = s3;
        #pragma unroll
        for (int o = 1; o < 32; o <<= 1) {
            int t = __shfl_up_sync(0xFFFFFFFFu, x, o);
            if (lane >= o) x += t;
        }
        if (lane == 31) wsum[w] = x;
        __syncthreads();
        if (w == 0) {
            int ws = wsum[lane];
            #pragma unroll
            for (int o = 1; o < 32; o <<= 1) {
                int t = __shfl_up_sync(0xFFFFFFFFu, ws, o);
                if (lane >= o) ws += t;
            }
            wsum[lane] = ws;
        }
        __syncthreads();
        int c = s_carry;
        int ex = (x - s3) + (w ? wsum[w - 1] : 0) + c;
        int tile_total = wsum[31];
        if (i4 < NI4) {
            int o = i4 * 4;
            g_off[o + 1] = ex + s0;  g_off[o + 2] = ex + s1;
            g_off[o + 3] = ex + s2;  g_off[o + 4] = ex + s3;
            g_cursor[o] = ex;            g_cursor[o + 1] = ex + s0;
            g_cursor[o + 2] = ex + s1;   g_cursor[o + 3] = ex + s2;
        }
        __syncthreads();
        if (tid == 0) s_carry = c + tile_total;
        __syncthreads();
    }
}

// 8 edges/thread
__global__ void k_scatter(const int* __restrict__ ei) {
    int i = blockIdx.x * blockDim.x + threadIdx.x;
    if (i < N_EDGES / 8) {
        int4 s0 = ((const int4*)ei)[i * 2];
        int4 s1 = ((const int4*)ei)[i * 2 + 1];
        int4 d0 = ((const int4*)(ei + N_EDGES))[i * 2];
        int4 d1 = ((const int4*)(ei + N_EDGES))[i * 2 + 1];
        int p0 = atomicAdd(&g_cursor[s0.x], 1);
        int p1 = atomicAdd(&g_cursor[s0.y], 1);
        int p2 = atomicAdd(&g_cursor[s0.z], 1);
        int p3 = atomicAdd(&g_cursor[s0.w], 1);
        int p4 = atomicAdd(&g_cursor[s1.x], 1);
        int p5 = atomicAdd(&g_cursor[s1.y], 1);
        int p6 = atomicAdd(&g_cursor[s1.z], 1);
        int p7 = atomicAdd(&g_cursor[s1.w], 1);
        g_csr[p0] = d0.x; g_csr[p1] = d0.y; g_csr[p2] = d0.z; g_csr[p3] = d0.w;
        g_csr[p4] = d1.x; g_csr[p5] = d1.y; g_csr[p6] = d1.z; g_csr[p7] = d1.w;
    }
}

// ====================== fused embed + interact-GEMM(0) =====================
__global__ __launch_bounds__(640) void k_embed_ab(
    const float* __restrict__ oh, const float* __restrict__ pos,
    const float* __restrict__ embW, const float* __restrict__ embB,
    const float* __restrict__ Wab0) {
    extern __shared__ float smem[];
    float* Ws   = smem;               // 7744
    float* Wab  = smem + 7744;        // 8192
    float* in_s = smem + 7744 + 8192; // 4840
    float* xs   = in_s + 4840;        // 2560
    const int tid = threadIdx.x;
    const int node0 = blockIdx.x * 40;
    {
        float4* d = (float4*)Ws; const float4* s = (const float4*)embW;
        for (int i = tid; i < 7744 / 4; i += 640) d[i] = s[i];
        float4* d2 = (float4*)Wab; const float4* s2 = (const float4*)Wab0;
        for (int i = tid; i < 8192 / 4; i += 640) d2[i] = s2[i];
    }
    for (int i = tid; i < 40 * 118; i += 640) {
        int row = i / 118, k = i % 118;
        in_s[row * 121 + k] = oh[(size_t)(node0 + row) * 118 + k];
    }
    for (int i = tid; i < 40 * 3; i += 640) {
        int row = i / 3, k = i % 3;
        in_s[row * 121 + 118 + k] = pos[(size_t)(node0 + row) * 3 + k];
    }
    __syncthreads();
    const int r = tid >> 4, cg = tid & 15;
    const int node = node0 + r;
    const float4* Ws4 = (const float4*)Ws;
    float4 acc = __ldg((const float4*)(embB) + cg);
    #pragma unroll 8
    for (int k = 0; k < 121; k++) {
        float h = in_s[r * 121 + k];
        float4 w = Ws4[k * 16 + cg];
        acc.x = fmaf(h, w.x, acc.x); acc.y = fmaf(h, w.y, acc.y);
        acc.z = fmaf(h, w.z, acc.z); acc.w = fmaf(h, w.w, acc.w);
    }
    float4 xv = silu4(acc);
    *(float4*)(g_x0 + (size_t)node * 64 + cg * 4) = xv;
    *(float4*)(g_x  + (size_t)node * 64 + cg * 4) = xv;
    ((float4*)xs)[r * 16 + cg] = xv;
    __syncthreads();
    const float4* Wa4 = (const float4*)Wab;
    const float4* Wb4 = Wa4 + 1024;
    float4 a4 = make_float4(0, 0, 0, 0), b4 = a4;
    #pragma unroll 8
    for (int k = 0; k < 64; k++) {
        float x = xs[r * 64 + k];
        float4 wa = Wa4[k * 16 + cg], wb = Wb4[k * 16 + cg];
        a4.x = fmaf(x, wa.x, a4.x); a4.y = fmaf(x, wa.y, a4.y);
        a4.z = fmaf(x, wa.z, a4.z); a4.w = fmaf(x, wa.w, a4.w);
        b4.x = fmaf(x, wb.x, b4.x); b4.y = fmaf(x, wb.y, b4.y);
        b4.z = fmaf(x, wb.z, b4.z); b4.w = fmaf(x, wb.w, b4.w);
    }
    *(float4*)(g_a + (size_t)node * 64 + cg * 4) = a4;
    *(float4*)(g_b + (size_t)node * 64 + cg * 4) = b4;
}

// ========================== CSR edge aggregation ===========================
// warp-per-node; 4 subgroups of 8 threads, one edge per subgroup.
// Each thread holds columns [c8*8, c8*8+8) as two float4s.
__global__ __launch_bounds__(256) void k_edge(const float* __restrict__ bias) {
    const int s = (blockIdx.x * 256 + threadIdx.x) >> 5;
    if (s >= N_NODES) return;
    const int lane = threadIdx.x & 31;
    const int sub = lane >> 3;          // 0..3: edge slot
    const int c8 = lane & 7;            // column group
    const float* arow = g_a + (size_t)s * 64 + c8 * 8;
    float4 aA = add4(*(const float4*)arow,       __ldg((const float4*)bias + c8 * 2));
    float4 aB = add4(*(const float4*)(arow + 4), __ldg((const float4*)bias + c8 * 2 + 1));
    const int j0 = g_off[s], end = g_off[s + 1];
    float4 accA = make_float4(0, 0, 0, 0), accB = accA;
    int j = j0 + sub;
    for (; j + 4 < end; j += 8) {
        int d0 = __ldg(g_csr + j);
        int d1 = __ldg(g_csr + j + 4);
        const float* b0 = g_b + (size_t)d0 * 64 + c8 * 8;
        const float* b1 = g_b + (size_t)d1 * 64 + c8 * 8;
        float4 bA0 = *(const float4*)b0, bB0 = *(const float4*)(b0 + 4);
        float4 bA1 = *(const float4*)b1, bB1 = *(const float4*)(b1 + 4);
        accA = add4(accA, silu4(add4(aA, bA0)));
        accB = add4(accB, silu4(add4(aB, bB0)));
        accA = add4(accA, silu4(add4(aA, bA1)));
        accB = add4(accB, silu4(add4(aB, bB1)));
    }
    if (j < end) {
        int d = __ldg(g_csr + j);
        const float* b0 = g_b + (size_t)d * 64 + c8 * 8;
        float4 bA0 = *(const float4*)b0, bB0 = *(const float4*)(b0 + 4);
        accA = add4(accA, silu4(add4(aA, bA0)));
        accB = add4(accB, silu4(add4(aB, bB0)));
    }
    // reduce across the 4 subgroups (xor 8, 16)
    #pragma unroll
    for (int o = 8; o <= 16; o <<= 1) {
        accA.x += __shfl_xor_sync(0xFFFFFFFFu, accA.x, o);
        accA.y += __shfl_xor_sync(0xFFFFFFFFu, accA.y, o);
        accA.z += __shfl_xor_sync(0xFFFFFFFFu, accA.z, o);
        accA.w += __shfl_xor_sync(0xFFFFFFFFu, accA.w, o);
        accB.x += __shfl_xor_sync(0xFFFFFFFFu, accB.x, o);
        accB.y += __shfl_xor_sync(0xFFFFFFFFu, accB.y, o);
        accB.z += __shfl_xor_sync(0xFFFFFFFFu, accB.z, o);
        accB.w += __shfl_xor_sync(0xFFFFFFFFu, accB.w, o);
    }
    if (sub == 0) {
        float* o = g_acc + (size_t)s * 64 + c8 * 8;
        *(float4*)o = accA;
        *(float4*)(o + 4) = accB;
    }
}

// =================== fused update(l) + interact-GEMM(l+1) ==================
// 80 nodes/block, 640 threads; thread = 2 rows x 4 cols.
__global__ __launch_bounds__(640) void k_update_ab(
    const float* __restrict__ U, const float* __restrict__ ub,
    const float* __restrict__ Wabn) {
    extern __shared__ float smem[];
    float* Us  = smem;
    float* Wab = smem + 4096;
    float* xs  = smem + 4096 + 8192;
    float* hs  = xs + 5120;
    const int tid = threadIdx.x;
    const int node0 = blockIdx.x * 80;
    {
        float4* d = (float4*)Us; const float4* s = (const float4*)U;
        for (int i = tid; i < 1024; i += 640) d[i] = s[i];
        float4* d2 = (float4*)Wab; const float4* s2 = (const float4*)Wabn;
        for (int i = tid; i < 2048; i += 640) d2[i] = s2[i];
    }
    for (int i = tid; i < 1280; i += 640) {
        int row = i >> 4, c4 = i & 15;
        float4 xv = *(const float4*)(g_x   + (size_t)(node0 + row) * 64 + c4 * 4);
        float4 av = *(const float4*)(g_acc + (size_t)(node0 + row) * 64 + c4 * 4);
        ((float4*)xs)[i] = xv;
        ((float4*)hs)[i] = make_float4(xv.x + 0.25f * av.x, xv.y + 0.25f * av.y,
                                       xv.z + 0.25f * av.z, xv.w + 0.25f * av.w);
    }
    __syncthreads();
    const int rl = tid >> 4, cg = tid & 15;
    const float4* Us4 = (const float4*)Us;
    float4 bias4 = __ldg((const float4*)(ub) + cg);
    float4 acc0 = bias4, acc1 = bias4;
    #pragma unroll 8
    for (int k = 0; k < 64; k++) {
        float4 w = Us4[k * 16 + cg];
        float h0 = hs[rl * 64 + k];
        float h1 = hs[(rl + 40) * 64 + k];
        acc0.x = fmaf(h0, w.x, acc0.x); acc0.y = fmaf(h0, w.y, acc0.y);
        acc0.z = fmaf(h0, w.z, acc0.z); acc0.w = fmaf(h0, w.w, acc0.w);
        acc1.x = fmaf(h1, w.x, acc1.x); acc1.y = fmaf(h1, w.y, acc1.y);
        acc1.z = fmaf(h1, w.z, acc1.z); acc1.w = fmaf(h1, w.w, acc1.w);
    }
    float4 sv0 = silu4(acc0), sv1 = silu4(acc1);
    float4 xo0 = ((float4*)xs)[rl * 16 + cg];
    float4 xo1 = ((float4*)xs)[(rl + 40) * 16 + cg];
    float4 xn0 = add4(xo0, sv0), xn1 = add4(xo1, sv1);
    *(float4*)(g_x + (size_t)(node0 + rl) * 64 + cg * 4) = xn0;
    *(float4*)(g_x + (size_t)(node0 + rl + 40) * 64 + cg * 4) = xn1;
    ((float4*)xs)[rl * 16 + cg] = xn0;
    ((float4*)xs)[(rl + 40) * 16 + cg] = xn1;
    __syncthreads();
    const float4* Wa4 = (const float4*)Wab;
    const float4* Wb4 = Wa4 + 1024;
    float4 a0 = make_float4(0, 0, 0, 0), b0 = a0, a1 = a0, b1 = a0;
    #pragma unroll 4
    for (int k = 0; k < 64; k++) {
        float4 wa = Wa4[k * 16 + cg], wb = Wb4[k * 16 + cg];
        float x0 = xs[rl * 64 + k];
        float x1 = xs[(rl + 40) * 64 + k];
        a0.x = fmaf(x0, wa.x, a0.x); a0.y = fmaf(x0, wa.y, a0.y);
        a0.z = fmaf(x0, wa.z, a0.z); a0.w = fmaf(x0, wa.w, a0.w);
        b0.x = fmaf(x0, wb.x, b0.x); b0.y = fmaf(x0, wb.y, b0.y);
        b0.z = fmaf(x0, wb.z, b0.z); b0.w = fmaf(x0, wb.w, b0.w);
        a1.x = fmaf(x1, wa.x, a1.x); a1.y = fmaf(x1, wa.y, a1.y);
        a1.z = fmaf(x1, wa.z, a1.z); a1.w = fmaf(x1, wa.w, a1.w);
        b1.x = fmaf(x1, wb.x, b1.x); b1.y = fmaf(x1, wb.y, b1.y);
        b1.z = fmaf(x1, wb.z, b1.z); b1.w = fmaf(x1, wb.w, b1.w);
    }
    *(float4*)(g_a + (size_t)(node0 + rl) * 64 + cg * 4) = a0;
    *(float4*)(g_b + (size_t)(node0 + rl) * 64 + cg * 4) = b0;
    *(float4*)(g_a + (size_t)(node0 + rl + 40) * 64 + cg * 4) = a1;
    *(float4*)(g_b + (size_t)(node0 + rl + 40) * 64 + cg * 4) = b1;
}

// ====================== fused update(3) + output head ======================
__global__ __launch_bounds__(640) void k_update_out(
    const float* __restrict__ U, const float* __restrict__ ub,
    const float* __restrict__ Wo, const float* __restrict__ bo,
    float* __restrict__ out) {
    __shared__ float Us[4096];
    __shared__ float xs[2560];
    __shared__ float hs[2560];
    __shared__ float Wos[192];
    const int tid = threadIdx.x;
    const int node0 = blockIdx.x * 40;
    {
        float4* d = (float4*)Us; const float4* s = (const float4*)U;
        for (int i = tid; i < 1024; i += 640) d[i] = s[i];
        if (tid < 192) Wos[tid] = Wo[tid];
    }
    {
        int row = tid >> 4, c4 = tid & 15;
        float4 xv = *(const float4*)(g_x   + (size_t)(node0 + row) * 64 + c4 * 4);
        float4 av = *(const float4*)(g_acc + (size_t)(node0 + row) * 64 + c4 * 4);
        ((float4*)xs)[tid] = xv;
        ((float4*)hs)[tid] = make_float4(xv.x + 0.25f * av.x, xv.y + 0.25f * av.y,
                                         xv.z + 0.25f * av.z, xv.w + 0.25f * av.w);
    }
    __syncthreads();
    const int r = tid >> 4, cg = tid & 15;
    const int node = node0 + r;
    const float4* Us4 = (const float4*)Us;
    float4 acc = __ldg((const float4*)(ub) + cg);
    #pragma unroll 8
    for (int k = 0; k < 64; k++) {
        float h = hs[r * 64 + k];
        float4 w = Us4[k * 16 + cg];
        acc.x = fmaf(h, w.x, acc.x); acc.y = fmaf(h, w.y, acc.y);
        acc.z = fmaf(h, w.z, acc.z); acc.w = fmaf(h, w.w, acc.w);
    }
    float4 sv = silu4(acc);
    float4 xo = ((float4*)xs)[r * 16 + cg];
    float4 x0v = *(const float4*)(g_x0 + (size_t)node * 64 + cg * 4);
    float4 v = make_float4(x0v.x + xo.x + sv.x, x0v.y + xo.y + sv.y,
                           x0v.z + xo.z + sv.z, x0v.w + xo.w + sv.w);
    float p0, p1, p2;
    const int cb = cg * 4;
    p0 = v.x * Wos[(cb + 0) * 3 + 0] + v.y * Wos[(cb + 1) * 3 + 0]
       + v.z * Wos[(cb + 2) * 3 + 0] + v.w * Wos[(cb + 3) * 3 + 0];
    p1 = v.x * Wos[(cb + 0) * 3 + 1] + v.y * Wos[(cb + 1) * 3 + 1]
       + v.z * Wos[(cb + 2) * 3 + 1] + v.w * Wos[(cb + 3) * 3 + 1];
    p2 = v.x * Wos[(cb + 0) * 3 + 2] + v.y * Wos[(cb + 1) * 3 + 2]
       + v.z * Wos[(cb + 2) * 3 + 2] + v.w * Wos[(cb + 3) * 3 + 2];
    #pragma unroll
    for (int off = 8; off > 0; off >>= 1) {
        p0 += __shfl_down_sync(0xFFFFFFFFu, p0, off, 16);
        p1 += __shfl_down_sync(0xFFFFFFFFu, p1, off, 16);
        p2 += __shfl_down_sync(0xFFFFFFFFu, p2, off, 16);
    }
    if (cg == 0) {
        out[node * 3 + 0] = p0 + __ldg(bo + 0);
        out[node * 3 + 1] = p1 + __ldg(bo + 1);
        out[node * 3 + 2] = p2 + __ldg(bo + 2);
    }
}

// ================================ launcher =================================
extern "C" void kernel_launch(void* const* d_in, const int* in_sizes, int n_in,
                              void* d_out, int out_size) {
    const float* oh   = (const float*)d_in[0];
    const float* pos  = (const float*)d_in[1];
    const int*   ei   = (const int*)d_in[2];
    const float* embW = (const float*)d_in[3];
    const float* embB = (const float*)d_in[4];
    const float* iW   = (const float*)d_in[5];   // [4, 128, 64]
    const float* iB   = (const float*)d_in[6];   // [4, 64]
    const float* uW   = (const float*)d_in[7];   // [4, 64, 64]
    const float* uB   = (const float*)d_in[8];   // [4, 64]
    const float* oW   = (const float*)d_in[9];   // [64, 3]
    const float* oB   = (const float*)d_in[10];  // [3]
    float* out = (float*)d_out;

    const int EMBED_SMEM  = (7744 + 8192 + 4840 + 2560) * 4;  // 93,344 B
    const int UPDATE_SMEM = (4096 + 8192 + 5120 + 5120) * 4;  // 90,112 B
    cudaFuncSetAttribute(k_embed_ab,  cudaFuncAttributeMaxDynamicSharedMemorySize, EMBED_SMEM);
    cudaFuncSetAttribute(k_update_ab, cudaFuncAttributeMaxDynamicSharedMemorySize, UPDATE_SMEM);

    k_zero_deg<<<(N_NODES + 255) / 256, 256>>>();
    k_hist<<<(N_EDGES / 8 + 255) / 256, 256>>>(ei);
    k_scan<<<1, 1024>>>();
    k_scatter<<<(N_EDGES / 8 + 255) / 256, 256>>>(ei);

    k_embed_ab<<<N_NODES / 40, 640, EMBED_SMEM>>>(oh, pos, embW, embB, iW);
    for (int l = 0; l < 4; l++) {
        k_edge<<<(N_NODES * 32 + 255) / 256, 256>>>(iB + l * 64);
        if (l < 3)
            k_update_ab<<<N_NODES / 80, 640, UPDATE_SMEM>>>(
                uW + (size_t)l * 4096, uB + l * 64, iW + (size_t)(l + 1) * 8192);
        else
            k_update_out<<<N_NODES / 40, 640>>>(
                uW + (size_t)l * 4096, uB + l * 64, oW, oB, out);
    }
}

// round 7
// speedup vs baseline: 1.0447x; 1.0447x over previous
#include <cuda_runtime.h>
#include <cstdint>

#define N_NODES 50000
#define N_EDGES 800000
#define H 64

// ---------------- scratch (device globals; no allocations) ----------------
__device__ __align__(16) float g_x0 [N_NODES * H];
__device__ __align__(16) float g_x  [N_NODES * H];
__device__ __align__(16) float g_a  [N_NODES * H];
__device__ __align__(16) float g_b  [N_NODES * H];
__device__ __align__(16) float g_acc[N_NODES * H];
__device__ __align__(16) int g_deg[N_NODES];
__device__ int g_off[N_NODES + 1];
__device__ int g_cursor[N_NODES];
__device__ int g_csr[N_EDGES];

// silu(z) = 0.5*z*(1 + tanh(z/2)) -- single MUFU.TANH
__device__ __forceinline__ float silu_f(float z) {
    float t;
    asm("tanh.approx.f32 %0, %1;" : "=f"(t) : "f"(0.5f * z));
    return 0.5f * z * (1.0f + t);
}
__device__ __forceinline__ float4 silu4(float4 z) {
    return make_float4(silu_f(z.x), silu_f(z.y), silu_f(z.z), silu_f(z.w));
}
__device__ __forceinline__ float4 add4(float4 a, float4 b) {
    return make_float4(a.x + b.x, a.y + b.y, a.z + b.z, a.w + b.w);
}

// ============================ CSR construction =============================
__global__ void k_zero_deg() {
    int i = blockIdx.x * blockDim.x + threadIdx.x;
    if (i < N_NODES) g_deg[i] = 0;
}

// 4 edges/thread for MLP on the atomics
__global__ void k_hist(const int* __restrict__ ei) {
    int i = blockIdx.x * blockDim.x + threadIdx.x;
    if (i < N_EDGES / 4) {
        int4 v = ((const int4*)ei)[i];
        atomicAdd(&g_deg[v.x], 1);
        atomicAdd(&g_deg[v.y], 1);
        atomicAdd(&g_deg[v.z], 1);
        atomicAdd(&g_deg[v.w], 1);
    }
}

// single-block scan, 4 elements/thread
__global__ __launch_bounds__(1024) void k_scan() {
    __shared__ int wsum[32];
    __shared__ int s_carry;
    const int tid = threadIdx.x, lane = tid & 31, w = tid >> 5;
    if (tid == 0) { g_off[0] = 0; s_carry = 0; }
    __syncthreads();
    const int NI4 = N_NODES / 4;  // 12500
    for (int base = 0; base < NI4; base += 1024) {
        int i4 = base + tid;
        int4 v = make_int4(0, 0, 0, 0);
        if (i4 < NI4) v = ((const int4*)g_deg)[i4];
        int s0 = v.x, s1 = s0 + v.y, s2 = s1 + v.z, s3 = s2 + v.w;
        int x = s3;
        #pragma unroll
        for (int o = 1; o < 32; o <<= 1) {
            int t = __shfl_up_sync(0xFFFFFFFFu, x, o);
            if (lane >= o) x += t;
        }
        if (lane == 31) wsum[w] = x;
        __syncthreads();
        if (w == 0) {
            int ws = wsum[lane];
            #pragma unroll
            for (int o = 1; o < 32; o <<= 1) {
                int t = __shfl_up_sync(0xFFFFFFFFu, ws, o);
                if (lane >= o) ws += t;
            }
            wsum[lane] = ws;
        }
        __syncthreads();
        int c = s_carry;
        int ex = (x - s3) + (w ? wsum[w - 1] : 0) + c;
        int tile_total = wsum[31];
        if (i4 < NI4) {
            int o = i4 * 4;
            g_off[o + 1] = ex + s0;  g_off[o + 2] = ex + s1;
            g_off[o + 3] = ex + s2;  g_off[o + 4] = ex + s3;
            g_cursor[o] = ex;            g_cursor[o + 1] = ex + s0;
            g_cursor[o + 2] = ex + s1;   g_cursor[o + 3] = ex + s2;
        }
        __syncthreads();
        if (tid == 0) s_carry = c + tile_total;
        __syncthreads();
    }
}

// 4 edges/thread
__global__ void k_scatter(const int* __restrict__ ei) {
    int i = blockIdx.x * blockDim.x + threadIdx.x;
    if (i < N_EDGES / 4) {
        int4 s = ((const int4*)ei)[i];
        int4 d = ((const int4*)(ei + N_EDGES))[i];
        int p0 = atomicAdd(&g_cursor[s.x], 1);
        int p1 = atomicAdd(&g_cursor[s.y], 1);
        int p2 = atomicAdd(&g_cursor[s.z], 1);
        int p3 = atomicAdd(&g_cursor[s.w], 1);
        g_csr[p0] = d.x; g_csr[p1] = d.y; g_csr[p2] = d.z; g_csr[p3] = d.w;
    }
}

// ====================== fused embed + interact-GEMM(0) =====================
__global__ __launch_bounds__(640) void k_embed_ab(
    const float* __restrict__ oh, const float* __restrict__ pos,
    const float* __restrict__ embW, const float* __restrict__ embB,
    const float* __restrict__ Wab0) {
    extern __shared__ float smem[];
    float* Ws   = smem;               // 7744
    float* Wab  = smem + 7744;        // 8192
    float* in_s = smem + 7744 + 8192; // 4840
    float* xs   = in_s + 4840;        // 2560
    const int tid = threadIdx.x;
    const int node0 = blockIdx.x * 40;
    {
        float4* d = (float4*)Ws; const float4* s = (const float4*)embW;
        for (int i = tid; i < 7744 / 4; i += 640) d[i] = s[i];
        float4* d2 = (float4*)Wab; const float4* s2 = (const float4*)Wab0;
        for (int i = tid; i < 8192 / 4; i += 640) d2[i] = s2[i];
    }
    for (int i = tid; i < 40 * 118; i += 640) {
        int row = i / 118, k = i % 118;
        in_s[row * 121 + k] = oh[(size_t)(node0 + row) * 118 + k];
    }
    for (int i = tid; i < 40 * 3; i += 640) {
        int row = i / 3, k = i % 3;
        in_s[row * 121 + 118 + k] = pos[(size_t)(node0 + row) * 3 + k];
    }
    __syncthreads();
    const int r = tid >> 4, cg = tid & 15;
    const int node = node0 + r;
    const float4* Ws4 = (const float4*)Ws;
    float4 acc = __ldg((const float4*)(embB) + cg);
    #pragma unroll 8
    for (int k = 0; k < 121; k++) {
        float h = in_s[r * 121 + k];
        float4 w = Ws4[k * 16 + cg];
        acc.x = fmaf(h, w.x, acc.x); acc.y = fmaf(h, w.y, acc.y);
        acc.z = fmaf(h, w.z, acc.z); acc.w = fmaf(h, w.w, acc.w);
    }
    float4 xv = silu4(acc);
    *(float4*)(g_x0 + (size_t)node * 64 + cg * 4) = xv;
    *(float4*)(g_x  + (size_t)node * 64 + cg * 4) = xv;
    ((float4*)xs)[r * 16 + cg] = xv;
    __syncthreads();
    const float4* Wa4 = (const float4*)Wab;
    const float4* Wb4 = Wa4 + 1024;
    float4 a4 = make_float4(0, 0, 0, 0), b4 = a4;
    #pragma unroll 8
    for (int k = 0; k < 64; k++) {
        float x = xs[r * 64 + k];
        float4 wa = Wa4[k * 16 + cg], wb = Wb4[k * 16 + cg];
        a4.x = fmaf(x, wa.x, a4.x); a4.y = fmaf(x, wa.y, a4.y);
        a4.z = fmaf(x, wa.z, a4.z); a4.w = fmaf(x, wa.w, a4.w);
        b4.x = fmaf(x, wb.x, b4.x); b4.y = fmaf(x, wb.y, b4.y);
        b4.z = fmaf(x, wb.z, b4.z); b4.w = fmaf(x, wb.w, b4.w);
    }
    *(float4*)(g_a + (size_t)node * 64 + cg * 4) = a4;
    *(float4*)(g_b + (size_t)node * 64 + cg * 4) = b4;
}

// ========================== CSR edge aggregation ===========================
// acc[s] = sum_{d in N(s)} silu(a[s] + b[d] + bias)
// 16 threads x float4 per node; unroll 4 -> 4 gathers in flight per group
__global__ __launch_bounds__(512) void k_edge(const float* __restrict__ bias) {
    const int tid = threadIdx.x;
    const int s = blockIdx.x * 32 + (tid >> 4);
    if (s >= N_NODES) return;
    const int c4 = tid & 15;
    float4 a4 = *(const float4*)(g_a + (size_t)s * 64 + c4 * 4);
    a4 = add4(a4, __ldg((const float4*)bias + c4));
    int j = g_off[s];
    const int end = g_off[s + 1];
    float4 acc = make_float4(0, 0, 0, 0);
    for (; j + 3 < end; j += 4) {
        int d0 = __ldg(g_csr + j);
        int d1 = __ldg(g_csr + j + 1);
        int d2 = __ldg(g_csr + j + 2);
        int d3 = __ldg(g_csr + j + 3);
        float4 b0 = *(const float4*)(g_b + (size_t)d0 * 64 + c4 * 4);
        float4 b1 = *(const float4*)(g_b + (size_t)d1 * 64 + c4 * 4);
        float4 b2 = *(const float4*)(g_b + (size_t)d2 * 64 + c4 * 4);
        float4 b3 = *(const float4*)(g_b + (size_t)d3 * 64 + c4 * 4);
        acc = add4(acc, silu4(add4(a4, b0)));
        acc = add4(acc, silu4(add4(a4, b1)));
        acc = add4(acc, silu4(add4(a4, b2)));
        acc = add4(acc, silu4(add4(a4, b3)));
    }
    for (; j < end; ++j) {
        int d = __ldg(g_csr + j);
        float4 b0 = *(const float4*)(g_b + (size_t)d * 64 + c4 * 4);
        acc = add4(acc, silu4(add4(a4, b0)));
    }
    *(float4*)(g_acc + (size_t)s * 64 + c4 * 4) = acc;
}

// =================== fused update(l) + interact-GEMM(l+1) ==================
// 80 nodes/block, 640 threads; thread = 2 rows x 4 cols.
__global__ __launch_bounds__(640) void k_update_ab(
    const float* __restrict__ U, const float* __restrict__ ub,
    const float* __restrict__ Wabn) {
    extern __shared__ float smem[];
    float* Us  = smem;
    float* Wab = smem + 4096;
    float* xs  = smem + 4096 + 8192;
    float* hs  = xs + 5120;
    const int tid = threadIdx.x;
    const int node0 = blockIdx.x * 80;
    {
        float4* d = (float4*)Us; const float4* s = (const float4*)U;
        for (int i = tid; i < 1024; i += 640) d[i] = s[i];
        float4* d2 = (float4*)Wab; const float4* s2 = (const float4*)Wabn;
        for (int i = tid; i < 2048; i += 640) d2[i] = s2[i];
    }
    for (int i = tid; i < 1280; i += 640) {
        int row = i >> 4, c4 = i & 15;
        float4 xv = *(const float4*)(g_x   + (size_t)(node0 + row) * 64 + c4 * 4);
        float4 av = *(const float4*)(g_acc + (size_t)(node0 + row) * 64 + c4 * 4);
        ((float4*)xs)[i] = xv;
        ((float4*)hs)[i] = make_float4(xv.x + 0.25f * av.x, xv.y + 0.25f * av.y,
                                       xv.z + 0.25f * av.z, xv.w + 0.25f * av.w);
    }
    __syncthreads();
    const int rl = tid >> 4, cg = tid & 15;
    const float4* Us4 = (const float4*)Us;
    float4 bias4 = __ldg((const float4*)(ub) + cg);
    float4 acc0 = bias4, acc1 = bias4;
    #pragma unroll 8
    for (int k = 0; k < 64; k++) {
        float4 w = Us4[k * 16 + cg];
        float h0 = hs[rl * 64 + k];
        float h1 = hs[(rl + 40) * 64 + k];
        acc0.x = fmaf(h0, w.x, acc0.x); acc0.y = fmaf(h0, w.y, acc0.y);
        acc0.z = fmaf(h0, w.z, acc0.z); acc0.w = fmaf(h0, w.w, acc0.w);
        acc1.x = fmaf(h1, w.x, acc1.x); acc1.y = fmaf(h1, w.y, acc1.y);
        acc1.z = fmaf(h1, w.z, acc1.z); acc1.w = fmaf(h1, w.w, acc1.w);
    }
    float4 sv0 = silu4(acc0), sv1 = silu4(acc1);
    float4 xo0 = ((float4*)xs)[rl * 16 + cg];
    float4 xo1 = ((float4*)xs)[(rl + 40) * 16 + cg];
    float4 xn0 = add4(xo0, sv0), xn1 = add4(xo1, sv1);
    *(float4*)(g_x + (size_t)(node0 + rl) * 64 + cg * 4) = xn0;
    *(float4*)(g_x + (size_t)(node0 + rl + 40) * 64 + cg * 4) = xn1;
    ((float4*)xs)[rl * 16 + cg] = xn0;
    ((float4*)xs)[(rl + 40) * 16 + cg] = xn1;
    __syncthreads();
    const float4* Wa4 = (const float4*)Wab;
    const float4* Wb4 = Wa4 + 1024;
    float4 a0 = make_float4(0, 0, 0, 0), b0 = a0, a1 = a0, b1 = a0;
    #pragma unroll 4
    for (int k = 0; k < 64; k++) {
        float4 wa = Wa4[k * 16 + cg], wb = Wb4[k * 16 + cg];
        float x0 = xs[rl * 64 + k];
        float x1 = xs[(rl + 40) * 64 + k];
        a0.x = fmaf(x0, wa.x, a0.x); a0.y = fmaf(x0, wa.y, a0.y);
        a0.z = fmaf(x0, wa.z, a0.z); a0.w = fmaf(x0, wa.w, a0.w);
        b0.x = fmaf(x0, wb.x, b0.x); b0.y = fmaf(x0, wb.y, b0.y);
        b0.z = fmaf(x0, wb.z, b0.z); b0.w = fmaf(x0, wb.w, b0.w);
        a1.x = fmaf(x1, wa.x, a1.x); a1.y = fmaf(x1, wa.y, a1.y);
        a1.z = fmaf(x1, wa.z, a1.z); a1.w = fmaf(x1, wa.w, a1.w);
        b1.x = fmaf(x1, wb.x, b1.x); b1.y = fmaf(x1, wb.y, b1.y);
        b1.z = fmaf(x1, wb.z, b1.z); b1.w = fmaf(x1, wb.w, b1.w);
    }
    *(float4*)(g_a + (size_t)(node0 + rl) * 64 + cg * 4) = a0;
    *(float4*)(g_b + (size_t)(node0 + rl) * 64 + cg * 4) = b0;
    *(float4*)(g_a + (size_t)(node0 + rl + 40) * 64 + cg * 4) = a1;
    *(float4*)(g_b + (size_t)(node0 + rl + 40) * 64 + cg * 4) = b1;
}

// ====================== fused update(3) + output head ======================
__global__ __launch_bounds__(640) void k_update_out(
    const float* __restrict__ U, const float* __restrict__ ub,
    const float* __restrict__ Wo, const float* __restrict__ bo,
    float* __restrict__ out) {
    __shared__ float Us[4096];
    __shared__ float xs[2560];
    __shared__ float hs[2560];
    __shared__ float Wos[192];
    const int tid = threadIdx.x;
    const int node0 = blockIdx.x * 40;
    {
        float4* d = (float4*)Us; const float4* s = (const float4*)U;
        for (int i = tid; i < 1024; i += 640) d[i] = s[i];
        if (tid < 192) Wos[tid] = Wo[tid];
    }
    {
        int row = tid >> 4, c4 = tid & 15;
        float4 xv = *(const float4*)(g_x   + (size_t)(node0 + row) * 64 + c4 * 4);
        float4 av = *(const float4*)(g_acc + (size_t)(node0 + row) * 64 + c4 * 4);
        ((float4*)xs)[tid] = xv;
        ((float4*)hs)[tid] = make_float4(xv.x + 0.25f * av.x, xv.y + 0.25f * av.y,
                                         xv.z + 0.25f * av.z, xv.w + 0.25f * av.w);
    }
    __syncthreads();
    const int r = tid >> 4, cg = tid & 15;
    const int node = node0 + r;
    const float4* Us4 = (const float4*)Us;
    float4 acc = __ldg((const float4*)(ub) + cg);
    #pragma unroll 8
    for (int k = 0; k < 64; k++) {
        float h = hs[r * 64 + k];
        float4 w = Us4[k * 16 + cg];
        acc.x = fmaf(h, w.x, acc.x); acc.y = fmaf(h, w.y, acc.y);
        acc.z = fmaf(h, w.z, acc.z); acc.w = fmaf(h, w.w, acc.w);
    }
    float4 sv = silu4(acc);
    float4 xo = ((float4*)xs)[r * 16 + cg];
    float4 x0v = *(const float4*)(g_x0 + (size_t)node * 64 + cg * 4);
    float4 v = make_float4(x0v.x + xo.x + sv.x, x0v.y + xo.y + sv.y,
                           x0v.z + xo.z + sv.z, x0v.w + xo.w + sv.w);
    float p0, p1, p2;
    const int cb = cg * 4;
    p0 = v.x * Wos[(cb + 0) * 3 + 0] + v.y * Wos[(cb + 1) * 3 + 0]
       + v.z * Wos[(cb + 2) * 3 + 0] + v.w * Wos[(cb + 3) * 3 + 0];
    p1 = v.x * Wos[(cb + 0) * 3 + 1] + v.y * Wos[(cb + 1) * 3 + 1]
       + v.z * Wos[(cb + 2) * 3 + 1] + v.w * Wos[(cb + 3) * 3 + 1];
    p2 = v.x * Wos[(cb + 0) * 3 + 2] + v.y * Wos[(cb + 1) * 3 + 2]
       + v.z * Wos[(cb + 2) * 3 + 2] + v.w * Wos[(cb + 3) * 3 + 2];
    #pragma unroll
    for (int off = 8; off > 0; off >>= 1) {
        p0 += __shfl_down_sync(0xFFFFFFFFu, p0, off, 16);
        p1 += __shfl_down_sync(0xFFFFFFFFu, p1, off, 16);
        p2 += __shfl_down_sync(0xFFFFFFFFu, p2, off, 16);
    }
    if (cg == 0) {
        out[node * 3 + 0] = p0 + __ldg(bo + 0);
        out[node * 3 + 1] = p1 + __ldg(bo + 1);
        out[node * 3 + 2] = p2 + __ldg(bo + 2);
    }
}

// ================================ launcher =================================
extern "C" void kernel_launch(void* const* d_in, const int* in_sizes, int n_in,
                              void* d_out, int out_size) {
    const float* oh   = (const float*)d_in[0];
    const float* pos  = (const float*)d_in[1];
    const int*   ei   = (const int*)d_in[2];
    const float* embW = (const float*)d_in[3];
    const float* embB = (const float*)d_in[4];
    const float* iW   = (const float*)d_in[5];   // [4, 128, 64]
    const float* iB   = (const float*)d_in[6];   // [4, 64]
    const float* uW   = (const float*)d_in[7];   // [4, 64, 64]
    const float* uB   = (const float*)d_in[8];   // [4, 64]
    const float* oW   = (const float*)d_in[9];   // [64, 3]
    const float* oB   = (const float*)d_in[10];  // [3]
    float* out = (float*)d_out;

    const int EMBED_SMEM  = (7744 + 8192 + 4840 + 2560) * 4;  // 93,344 B
    const int UPDATE_SMEM = (4096 + 8192 + 5120 + 5120) * 4;  // 90,112 B
    cudaFuncSetAttribute(k_embed_ab,  cudaFuncAttributeMaxDynamicSharedMemorySize, EMBED_SMEM);
    cudaFuncSetAttribute(k_update_ab, cudaFuncAttributeMaxDynamicSharedMemorySize, UPDATE_SMEM);

    k_zero_deg<<<(N_NODES + 255) / 256, 256>>>();
    k_hist<<<(N_EDGES / 4 + 255) / 256, 256>>>(ei);
    k_scan<<<1, 1024>>>();
    k_scatter<<<(N_EDGES / 4 + 255) / 256, 256>>>(ei);

    k_embed_ab<<<N_NODES / 40, 640, EMBED_SMEM>>>(oh, pos, embW, embB, iW);
    for (int l = 0; l < 4; l++) {
        k_edge<<<(N_NODES + 31) / 32, 512>>>(iB + l * 64);
        if (l < 3)
            k_update_ab<<<N_NODES / 80, 640, UPDATE_SMEM>>>(
                uW + (size_t)l * 4096, uB + l * 64, iW + (size_t)(l + 1) * 8192);
        else
            k_update_out<<<N_NODES / 40, 640>>>(
                uW + (size_t)l * 4096, uB + l * 64, oW, oB, out);
    }
}

// round 9
// speedup vs baseline: 1.1744x; 1.1242x over previous
#include <cuda_runtime.h>
#include <cstdint>

#define N_NODES 50000
#define N_EDGES 800000
#define H 64

// ---------------- scratch (device globals; no allocations) ----------------
__device__ __align__(16) float g_x0 [N_NODES * H];
__device__ __align__(16) float g_x  [N_NODES * H];
__device__ __align__(16) float g_a  [N_NODES * H];
__device__ __align__(16) float g_b  [N_NODES * H];
__device__ __align__(16) float g_acc[N_NODES * H];
__device__ __align__(16) int g_deg[N_NODES];     // static-zero; re-zeroed by k_scan
__device__ int g_off[N_NODES + 1];
__device__ int g_cursor[N_NODES];
__device__ int g_csr[N_EDGES];

// silu(z) = 0.5*z*(1 + tanh(z/2)) -- single MUFU.TANH
__device__ __forceinline__ float silu_f(float z) {
    float t;
    asm("tanh.approx.f32 %0, %1;" : "=f"(t) : "f"(0.5f * z));
    return 0.5f * z * (1.0f + t);
}
__device__ __forceinline__ float4 silu4(float4 z) {
    return make_float4(silu_f(z.x), silu_f(z.y), silu_f(z.z), silu_f(z.w));
}
__device__ __forceinline__ float4 add4(float4 a, float4 b) {
    return make_float4(a.x + b.x, a.y + b.y, a.z + b.z, a.w + b.w);
}

// ============================ CSR construction =============================
// 4 edges/thread for MLP on the atomics
__global__ void k_hist(const int* __restrict__ ei) {
    int i = blockIdx.x * blockDim.x + threadIdx.x;
    if (i < N_EDGES / 4) {
        int4 v = ((const int4*)ei)[i];
        atomicAdd(&g_deg[v.x], 1);
        atomicAdd(&g_deg[v.y], 1);
        atomicAdd(&g_deg[v.z], 1);
        atomicAdd(&g_deg[v.w], 1);
    }
}

// single-block scan, 4 elements/thread; re-zeros g_deg for the next call
__global__ __launch_bounds__(1024) void k_scan() {
    __shared__ int wsum[32];
    __shared__ int s_carry;
    const int tid = threadIdx.x, lane = tid & 31, w = tid >> 5;
    if (tid == 0) { g_off[0] = 0; s_carry = 0; }
    __syncthreads();
    const int NI4 = N_NODES / 4;  // 12500
    for (int base = 0; base < NI4; base += 1024) {
        int i4 = base + tid;
        int4 v = make_int4(0, 0, 0, 0);
        if (i4 < NI4) {
            v = ((const int4*)g_deg)[i4];
            ((int4*)g_deg)[i4] = make_int4(0, 0, 0, 0);   // re-zero for next call
        }
        int s0 = v.x, s1 = s0 + v.y, s2 = s1 + v.z, s3 = s2 + v.w;
        int x = s3;
        #pragma unroll
        for (int o = 1; o < 32; o <<= 1) {
            int t = __shfl_up_sync(0xFFFFFFFFu, x, o);
            if (lane >= o) x += t;
        }
        if (lane == 31) wsum[w] = x;
        __syncthreads();
        if (w == 0) {
            int ws = wsum[lane];
            #pragma unroll
            for (int o = 1; o < 32; o <<= 1) {
                int t = __shfl_up_sync(0xFFFFFFFFu, ws, o);
                if (lane >= o) ws += t;
            }
            wsum[lane] = ws;
        }
        __syncthreads();
        int c = s_carry;
        int ex = (x - s3) + (w ? wsum[w - 1] : 0) + c;
        int tile_total = wsum[31];
        if (i4 < NI4) {
            int o = i4 * 4;
            g_off[o + 1] = ex + s0;  g_off[o + 2] = ex + s1;
            g_off[o + 3] = ex + s2;  g_off[o + 4] = ex + s3;
            g_cursor[o] = ex;            g_cursor[o + 1] = ex + s0;
            g_cursor[o + 2] = ex + s1;   g_cursor[o + 3] = ex + s2;
        }
        __syncthreads();
        if (tid == 0) s_carry = c + tile_total;
        __syncthreads();
    }
}

// 4 edges/thread
__global__ void k_scatter(const int* __restrict__ ei) {
    int i = blockIdx.x * blockDim.x + threadIdx.x;
    if (i < N_EDGES / 4) {
        int4 s = ((const int4*)ei)[i];
        int4 d = ((const int4*)(ei + N_EDGES))[i];
        int p0 = atomicAdd(&g_cursor[s.x], 1);
        int p1 = atomicAdd(&g_cursor[s.y], 1);
        int p2 = atomicAdd(&g_cursor[s.z], 1);
        int p3 = atomicAdd(&g_cursor[s.w], 1);
        g_csr[p0] = d.x; g_csr[p1] = d.y; g_csr[p2] = d.z; g_csr[p3] = d.w;
    }
}

// ====================== fused embed + interact-GEMM(0) =====================
__global__ __launch_bounds__(640) void k_embed_ab(
    const float* __restrict__ oh, const float* __restrict__ pos,
    const float* __restrict__ embW, const float* __restrict__ embB,
    const float* __restrict__ Wab0) {
    extern __shared__ float smem[];
    float* Ws   = smem;               // 7744
    float* Wab  = smem + 7744;        // 8192
    float* in_s = smem + 7744 + 8192; // 4840
    float* xs   = in_s + 4840;        // 2560
    const int tid = threadIdx.x;
    const int node0 = blockIdx.x * 40;
    {
        float4* d = (float4*)Ws; const float4* s = (const float4*)embW;
        for (int i = tid; i < 7744 / 4; i += 640) d[i] = s[i];
        float4* d2 = (float4*)Wab; const float4* s2 = (const float4*)Wab0;
        for (int i = tid; i < 8192 / 4; i += 640) d2[i] = s2[i];
    }
    for (int i = tid; i < 40 * 118; i += 640) {
        int row = i / 118, k = i % 118;
        in_s[row * 121 + k] = oh[(size_t)(node0 + row) * 118 + k];
    }
    for (int i = tid; i < 40 * 3; i += 640) {
        int row = i / 3, k = i % 3;
        in_s[row * 121 + 118 + k] = pos[(size_t)(node0 + row) * 3 + k];
    }
    __syncthreads();
    const int r = tid >> 4, cg = tid & 15;
    const int node = node0 + r;
    const float4* Ws4 = (const float4*)Ws;
    float4 acc = __ldg((const float4*)(embB) + cg);
    #pragma unroll 8
    for (int k = 0; k < 121; k++) {
        float h = in_s[r * 121 + k];
        float4 w = Ws4[k * 16 + cg];
        acc.x = fmaf(h, w.x, acc.x); acc.y = fmaf(h, w.y, acc.y);
        acc.z = fmaf(h, w.z, acc.z); acc.w = fmaf(h, w.w, acc.w);
    }
    float4 xv = silu4(acc);
    *(float4*)(g_x0 + (size_t)node * 64 + cg * 4) = xv;
    *(float4*)(g_x  + (size_t)node * 64 + cg * 4) = xv;
    ((float4*)xs)[r * 16 + cg] = xv;
    __syncthreads();
    const float4* Wa4 = (const float4*)Wab;
    const float4* Wb4 = Wa4 + 1024;
    float4 a4 = make_float4(0, 0, 0, 0), b4 = a4;
    #pragma unroll 8
    for (int k = 0; k < 64; k++) {
        float x = xs[r * 64 + k];
        float4 wa = Wa4[k * 16 + cg], wb = Wb4[k * 16 + cg];
        a4.x = fmaf(x, wa.x, a4.x); a4.y = fmaf(x, wa.y, a4.y);
        a4.z = fmaf(x, wa.z, a4.z); a4.w = fmaf(x, wa.w, a4.w);
        b4.x = fmaf(x, wb.x, b4.x); b4.y = fmaf(x, wb.y, b4.y);
        b4.z = fmaf(x, wb.z, b4.z); b4.w = fmaf(x, wb.w, b4.w);
    }
    *(float4*)(g_a + (size_t)node * 64 + cg * 4) = a4;
    *(float4*)(g_b + (size_t)node * 64 + cg * 4) = b4;
}

// ========================== CSR edge aggregation ===========================
// (unchanged from R4/R7 — best measured variant)
__global__ __launch_bounds__(512) void k_edge(const float* __restrict__ bias) {
    const int tid = threadIdx.x;
    const int s = blockIdx.x * 32 + (tid >> 4);
    if (s >= N_NODES) return;
    const int c4 = tid & 15;
    float4 a4 = *(const float4*)(g_a + (size_t)s * 64 + c4 * 4);
    a4 = add4(a4, __ldg((const float4*)bias + c4));
    int j = g_off[s];
    const int end = g_off[s + 1];
    float4 acc = make_float4(0, 0, 0, 0);
    for (; j + 3 < end; j += 4) {
        int d0 = __ldg(g_csr + j);
        int d1 = __ldg(g_csr + j + 1);
        int d2 = __ldg(g_csr + j + 2);
        int d3 = __ldg(g_csr + j + 3);
        float4 b0 = *(const float4*)(g_b + (size_t)d0 * 64 + c4 * 4);
        float4 b1 = *(const float4*)(g_b + (size_t)d1 * 64 + c4 * 4);
        float4 b2 = *(const float4*)(g_b + (size_t)d2 * 64 + c4 * 4);
        float4 b3 = *(const float4*)(g_b + (size_t)d3 * 64 + c4 * 4);
        acc = add4(acc, silu4(add4(a4, b0)));
        acc = add4(acc, silu4(add4(a4, b1)));
        acc = add4(acc, silu4(add4(a4, b2)));
        acc = add4(acc, silu4(add4(a4, b3)));
    }
    for (; j < end; ++j) {
        int d = __ldg(g_csr + j);
        float4 b0 = *(const float4*)(g_b + (size_t)d * 64 + c4 * 4);
        acc = add4(acc, silu4(add4(a4, b0)));
    }
    *(float4*)(g_acc + (size_t)s * 64 + c4 * 4) = acc;
}

// =================== fused update(l) + interact-GEMM(l+1) ==================
// 100 nodes/block, 400 threads; thread = 4 rows x 4 cols.
// dyn smem: U[4096] | Wab[8192] | xs[6400] | hs[6400]  (100,352 B)
__global__ __launch_bounds__(400, 2) void k_update_ab(
    const float* __restrict__ U, const float* __restrict__ ub,
    const float* __restrict__ Wabn) {
    extern __shared__ float smem[];
    float* Us  = smem;
    float* Wab = smem + 4096;
    float* xs  = smem + 4096 + 8192;
    float* hs  = xs + 6400;
    const int tid = threadIdx.x;
    const int node0 = blockIdx.x * 100;
    {
        float4* d = (float4*)Us; const float4* s = (const float4*)U;
        for (int i = tid; i < 1024; i += 400) d[i] = s[i];
        float4* d2 = (float4*)Wab; const float4* s2 = (const float4*)Wabn;
        for (int i = tid; i < 2048; i += 400) d2[i] = s2[i];
    }
    for (int i = tid; i < 1600; i += 400) {
        int row = i >> 4, c4 = i & 15;
        float4 xv = *(const float4*)(g_x   + (size_t)(node0 + row) * 64 + c4 * 4);
        float4 av = *(const float4*)(g_acc + (size_t)(node0 + row) * 64 + c4 * 4);
        ((float4*)xs)[i] = xv;
        ((float4*)hs)[i] = make_float4(xv.x + 0.25f * av.x, xv.y + 0.25f * av.y,
                                       xv.z + 0.25f * av.z, xv.w + 0.25f * av.w);
    }
    __syncthreads();
    const int rl = tid >> 4, cg = tid & 15;   // rows rl+25*j, j=0..3
    const float4* Us4 = (const float4*)Us;
    const float4 ub4 = __ldg((const float4*)(ub) + cg);
    float4 acc0 = ub4, acc1 = ub4, acc2 = ub4, acc3 = ub4;
    #pragma unroll 4
    for (int k = 0; k < 64; k++) {
        float4 w = Us4[k * 16 + cg];
        float h0 = hs[rl * 64 + k];
        float h1 = hs[(rl + 25) * 64 + k];
        float h2 = hs[(rl + 50) * 64 + k];
        float h3 = hs[(rl + 75) * 64 + k];
        acc0.x = fmaf(h0, w.x, acc0.x); acc0.y = fmaf(h0, w.y, acc0.y);
        acc0.z = fmaf(h0, w.z, acc0.z); acc0.w = fmaf(h0, w.w, acc0.w);
        acc1.x = fmaf(h1, w.x, acc1.x); acc1.y = fmaf(h1, w.y, acc1.y);
        acc1.z = fmaf(h1, w.z, acc1.z); acc1.w = fmaf(h1, w.w, acc1.w);
        acc2.x = fmaf(h2, w.x, acc2.x); acc2.y = fmaf(h2, w.y, acc2.y);
        acc2.z = fmaf(h2, w.z, acc2.z); acc2.w = fmaf(h2, w.w, acc2.w);
        acc3.x = fmaf(h3, w.x, acc3.x); acc3.y = fmaf(h3, w.y, acc3.y);
        acc3.z = fmaf(h3, w.z, acc3.z); acc3.w = fmaf(h3, w.w, acc3.w);
    }
    #pragma unroll
    for (int jj = 0; jj < 4; jj++) {
        float4 accv = jj == 0 ? acc0 : jj == 1 ? acc1 : jj == 2 ? acc2 : acc3;
        int row = rl + 25 * jj;
        float4 xo = ((float4*)xs)[row * 16 + cg];
        float4 xn = add4(xo, silu4(accv));
        *(float4*)(g_x + (size_t)(node0 + row) * 64 + cg * 4) = xn;
        ((float4*)xs)[row * 16 + cg] = xn;
    }
    __syncthreads();
    const float4* Wa4 = (const float4*)Wab;
    const float4* Wb4 = Wa4 + 1024;
    float4 a0 = make_float4(0, 0, 0, 0), a1 = a0, a2 = a0, a3 = a0;
    float4 b0 = a0, b1 = a0, b2 = a0, b3 = a0;
    #pragma unroll 2
    for (int k = 0; k < 64; k++) {
        float4 wa = Wa4[k * 16 + cg], wb = Wb4[k * 16 + cg];
        float x0 = xs[rl * 64 + k];
        float x1 = xs[(rl + 25) * 64 + k];
        float x2 = xs[(rl + 50) * 64 + k];
        float x3 = xs[(rl + 75) * 64 + k];
        a0.x = fmaf(x0, wa.x, a0.x); a0.y = fmaf(x0, wa.y, a0.y);
        a0.z = fmaf(x0, wa.z, a0.z); a0.w = fmaf(x0, wa.w, a0.w);
        b0.x = fmaf(x0, wb.x, b0.x); b0.y = fmaf(x0, wb.y, b0.y);
        b0.z = fmaf(x0, wb.z, b0.z); b0.w = fmaf(x0, wb.w, b0.w);
        a1.x = fmaf(x1, wa.x, a1.x); a1.y = fmaf(x1, wa.y, a1.y);
        a1.z = fmaf(x1, wa.z, a1.z); a1.w = fmaf(x1, wa.w, a1.w);
        b1.x = fmaf(x1, wb.x, b1.x); b1.y = fmaf(x1, wb.y, b1.y);
        b1.z = fmaf(x1, wb.z, b1.z); b1.w = fmaf(x1, wb.w, b1.w);
        a2.x = fmaf(x2, wa.x, a2.x); a2.y = fmaf(x2, wa.y, a2.y);
        a2.z = fmaf(x2, wa.z, a2.z); a2.w = fmaf(x2, wa.w, a2.w);
        b2.x = fmaf(x2, wb.x, b2.x); b2.y = fmaf(x2, wb.y, b2.y);
        b2.z = fmaf(x2, wb.z, b2.z); b2.w = fmaf(x2, wb.w, b2.w);
        a3.x = fmaf(x3, wa.x, a3.x); a3.y = fmaf(x3, wa.y, a3.y);
        a3.z = fmaf(x3, wa.z, a3.z); a3.w = fmaf(x3, wa.w, a3.w);
        b3.x = fmaf(x3, wb.x, b3.x); b3.y = fmaf(x3, wb.y, b3.y);
        b3.z = fmaf(x3, wb.z, b3.z); b3.w = fmaf(x3, wb.w, b3.w);
    }
    #pragma unroll
    for (int jj = 0; jj < 4; jj++) {
        float4 av = jj == 0 ? a0 : jj == 1 ? a1 : jj == 2 ? a2 : a3;
        float4 bv = jj == 0 ? b0 : jj == 1 ? b1 : jj == 2 ? b2 : b3;
        int node = node0 + rl + 25 * jj;
        *(float4*)(g_a + (size_t)node * 64 + cg * 4) = av;
        *(float4*)(g_b + (size_t)node * 64 + cg * 4) = bv;
    }
}

// ====================== fused update(3) + output head ======================
// 100 nodes/block, 400 threads; thread = 4 rows x 4 cols.
// dyn smem: U[4096] | xs[6400] | hs[6400] | Wos[192]  (67,968 B)
__global__ __launch_bounds__(400, 2) void k_update_out(
    const float* __restrict__ U, const float* __restrict__ ub,
    const float* __restrict__ Wo, const float* __restrict__ bo,
    float* __restrict__ out) {
    extern __shared__ float smem[];
    float* Us  = smem;
    float* xs  = smem + 4096;
    float* hs  = xs + 6400;
    float* Wos = hs + 6400;
    const int tid = threadIdx.x;
    const int node0 = blockIdx.x * 100;
    {
        float4* d = (float4*)Us; const float4* s = (const float4*)U;
        for (int i = tid; i < 1024; i += 400) d[i] = s[i];
        if (tid < 192) Wos[tid] = Wo[tid];
    }
    for (int i = tid; i < 1600; i += 400) {
        int row = i >> 4, c4 = i & 15;
        float4 xv = *(const float4*)(g_x   + (size_t)(node0 + row) * 64 + c4 * 4);
        float4 av = *(const float4*)(g_acc + (size_t)(node0 + row) * 64 + c4 * 4);
        ((float4*)xs)[i] = xv;
        ((float4*)hs)[i] = make_float4(xv.x + 0.25f * av.x, xv.y + 0.25f * av.y,
                                       xv.z + 0.25f * av.z, xv.w + 0.25f * av.w);
    }
    __syncthreads();
    const int rl = tid >> 4, cg = tid & 15;
    const float4* Us4 = (const float4*)Us;
    const float4 ub4 = __ldg((const float4*)(ub) + cg);
    float4 acc0 = ub4, acc1 = ub4, acc2 = ub4, acc3 = ub4;
    #pragma unroll 4
    for (int k = 0; k < 64; k++) {
        float4 w = Us4[k * 16 + cg];
        float h0 = hs[rl * 64 + k];
        float h1 = hs[(rl + 25) * 64 + k];
        float h2 = hs[(rl + 50) * 64 + k];
        float h3 = hs[(rl + 75) * 64 + k];
        acc0.x = fmaf(h0, w.x, acc0.x); acc0.y = fmaf(h0, w.y, acc0.y);
        acc0.z = fmaf(h0, w.z, acc0.z); acc0.w = fmaf(h0, w.w, acc0.w);
        acc1.x = fmaf(h1, w.x, acc1.x); acc1.y = fmaf(h1, w.y, acc1.y);
        acc1.z = fmaf(h1, w.z, acc1.z); acc1.w = fmaf(h1, w.w, acc1.w);
        acc2.x = fmaf(h2, w.x, acc2.x); acc2.y = fmaf(h2, w.y, acc2.y);
        acc2.z = fmaf(h2, w.z, acc2.z); acc2.w = fmaf(h2, w.w, acc2.w);
        acc3.x = fmaf(h3, w.x, acc3.x); acc3.y = fmaf(h3, w.y, acc3.y);
        acc3.z = fmaf(h3, w.z, acc3.z); acc3.w = fmaf(h3, w.w, acc3.w);
    }
    #pragma unroll
    for (int jj = 0; jj < 4; jj++) {
        float4 accv = jj == 0 ? acc0 : jj == 1 ? acc1 : jj == 2 ? acc2 : acc3;
        int row = rl + 25 * jj;
        int node = node0 + row;
        float4 sv = silu4(accv);
        float4 xo = ((float4*)xs)[row * 16 + cg];
        float4 x0v = *(const float4*)(g_x0 + (size_t)node * 64 + cg * 4);
        float4 v = make_float4(x0v.x + xo.x + sv.x, x0v.y + xo.y + sv.y,
                               x0v.z + xo.z + sv.z, x0v.w + xo.w + sv.w);
        const int cb = cg * 4;
        float p0 = v.x * Wos[(cb + 0) * 3 + 0] + v.y * Wos[(cb + 1) * 3 + 0]
                 + v.z * Wos[(cb + 2) * 3 + 0] + v.w * Wos[(cb + 3) * 3 + 0];
        float p1 = v.x * Wos[(cb + 0) * 3 + 1] + v.y * Wos[(cb + 1) * 3 + 1]
                 + v.z * Wos[(cb + 2) * 3 + 1] + v.w * Wos[(cb + 3) * 3 + 1];
        float p2 = v.x * Wos[(cb + 0) * 3 + 2] + v.y * Wos[(cb + 1) * 3 + 2]
                 + v.z * Wos[(cb + 2) * 3 + 2] + v.w * Wos[(cb + 3) * 3 + 2];
        #pragma unroll
        for (int off = 8; off > 0; off >>= 1) {
            p0 += __shfl_down_sync(0xFFFFFFFFu, p0, off, 16);
            p1 += __shfl_down_sync(0xFFFFFFFFu, p1, off, 16);
            p2 += __shfl_down_sync(0xFFFFFFFFu, p2, off, 16);
        }
        if (cg == 0) {
            out[node * 3 + 0] = p0 + __ldg(bo + 0);
            out[node * 3 + 1] = p1 + __ldg(bo + 1);
            out[node * 3 + 2] = p2 + __ldg(bo + 2);
        }
    }
}

// ================================ launcher =================================
extern "C" void kernel_launch(void* const* d_in, const int* in_sizes, int n_in,
                              void* d_out, int out_size) {
    const float* oh   = (const float*)d_in[0];
    const float* pos  = (const float*)d_in[1];
    const int*   ei   = (const int*)d_in[2];
    const float* embW = (const float*)d_in[3];
    const float* embB = (const float*)d_in[4];
    const float* iW   = (const float*)d_in[5];   // [4, 128, 64]
    const float* iB   = (const float*)d_in[6];   // [4, 64]
    const float* uW   = (const float*)d_in[7];   // [4, 64, 64]
    const float* uB   = (const float*)d_in[8];   // [4, 64]
    const float* oW   = (const float*)d_in[9];   // [64, 3]
    const float* oB   = (const float*)d_in[10];  // [3]
    float* out = (float*)d_out;

    // Side stream + events, created on the first (uncaptured) correctness call.
    static cudaStream_t s2 = nullptr;
    static cudaEvent_t ev_fork = nullptr, ev_join = nullptr;
    static bool attrs_set = false;
    const int EMBED_SMEM  = (7744 + 8192 + 4840 + 2560) * 4;   // 93,344 B
    const int UPDATE_SMEM = (4096 + 8192 + 6400 + 6400) * 4;   // 100,352 B
    const int UOUT_SMEM   = (4096 + 6400 + 6400 + 192) * 4;    // 68,352 B
    if (!attrs_set) {
        cudaStreamCreateWithFlags(&s2, cudaStreamNonBlocking);
        cudaEventCreateWithFlags(&ev_fork, cudaEventDisableTiming);
        cudaEventCreateWithFlags(&ev_join, cudaEventDisableTiming);
        cudaFuncSetAttribute(k_embed_ab,  cudaFuncAttributeMaxDynamicSharedMemorySize, EMBED_SMEM);
        cudaFuncSetAttribute(k_update_ab, cudaFuncAttributeMaxDynamicSharedMemorySize, UPDATE_SMEM);
        cudaFuncSetAttribute(k_update_out,cudaFuncAttributeMaxDynamicSharedMemorySize, UOUT_SMEM);
        attrs_set = true;
    }

    // Fork: CSR build on s2, embed on legacy stream, join before first edge.
    cudaEventRecord(ev_fork, 0);
    cudaStreamWaitEvent(s2, ev_fork, 0);
    k_hist<<<(N_EDGES / 4 + 255) / 256, 256, 0, s2>>>(ei);
    k_scan<<<1, 1024, 0, s2>>>();
    k_scatter<<<(N_EDGES / 4 + 255) / 256, 256, 0, s2>>>(ei);
    cudaEventRecord(ev_join, s2);

    k_embed_ab<<<N_NODES / 40, 640, EMBED_SMEM>>>(oh, pos, embW, embB, iW);
    cudaStreamWaitEvent(0, ev_join, 0);

    for (int l = 0; l < 4; l++) {
        k_edge<<<(N_NODES + 31) / 32, 512>>>(iB + l * 64);
        if (l < 3)
            k_update_ab<<<N_NODES / 100, 400, UPDATE_SMEM>>>(
                uW + (size_t)l * 4096, uB + l * 64, iW + (size_t)(l + 1) * 8192);
        else
            k_update_out<<<N_NODES / 100, 400, UOUT_SMEM>>>(
                uW + (size_t)l * 4096, uB + l * 64, oW, oB, out);
    }
}

// round 11
// speedup vs baseline: 1.2682x; 1.0798x over previous
#include <cuda_runtime.h>
#include <cstdint>

#define N_NODES 50000
#define N_EDGES 800000
#define H 64

// ---------------- scratch (device globals; no allocations) ----------------
__device__ __align__(16) float g_x0 [N_NODES * H];
__device__ __align__(16) float g_x  [N_NODES * H];
__device__ __align__(16) float g_a  [N_NODES * H];
__device__ __align__(16) float g_b  [N_NODES * H];
__device__ __align__(16) float g_acc[N_NODES * H];
__device__ __align__(16) int g_deg[N_NODES];     // static-zero; re-zeroed by k_scan
__device__ int g_off[N_NODES + 1];
__device__ int g_cursor[N_NODES];
__device__ int g_csr[N_EDGES];

// silu(z) = 0.5*z*(1 + tanh(z/2)) -- single MUFU.TANH
__device__ __forceinline__ float silu_f(float z) {
    float t;
    asm("tanh.approx.f32 %0, %1;" : "=f"(t) : "f"(0.5f * z));
    return 0.5f * z * (1.0f + t);
}
__device__ __forceinline__ float4 silu4(float4 z) {
    return make_float4(silu_f(z.x), silu_f(z.y), silu_f(z.z), silu_f(z.w));
}
__device__ __forceinline__ float4 add4(float4 a, float4 b) {
    return make_float4(a.x + b.x, a.y + b.y, a.z + b.z, a.w + b.w);
}

// ============================ CSR construction =============================
__global__ void k_hist(const int* __restrict__ ei) {
    int i = blockIdx.x * blockDim.x + threadIdx.x;
    if (i < N_EDGES / 4) {
        int4 v = ((const int4*)ei)[i];
        atomicAdd(&g_deg[v.x], 1);
        atomicAdd(&g_deg[v.y], 1);
        atomicAdd(&g_deg[v.z], 1);
        atomicAdd(&g_deg[v.w], 1);
    }
}

__global__ __launch_bounds__(1024) void k_scan() {
    __shared__ int wsum[32];
    __shared__ int s_carry;
    const int tid = threadIdx.x, lane = tid & 31, w = tid >> 5;
    if (tid == 0) { g_off[0] = 0; s_carry = 0; }
    __syncthreads();
    const int NI4 = N_NODES / 4;  // 12500
    for (int base = 0; base < NI4; base += 1024) {
        int i4 = base + tid;
        int4 v = make_int4(0, 0, 0, 0);
        if (i4 < NI4) {
            v = ((const int4*)g_deg)[i4];
            ((int4*)g_deg)[i4] = make_int4(0, 0, 0, 0);   // re-zero for next call
        }
        int s0 = v.x, s1 = s0 + v.y, s2 = s1 + v.z, s3 = s2 + v.w;
        int x = s3;
        #pragma unroll
        for (int o = 1; o < 32; o <<= 1) {
            int t = __shfl_up_sync(0xFFFFFFFFu, x, o);
            if (lane >= o) x += t;
        }
        if (lane == 31) wsum[w] = x;
        __syncthreads();
        if (w == 0) {
            int ws = wsum[lane];
            #pragma unroll
            for (int o = 1; o < 32; o <<= 1) {
                int t = __shfl_up_sync(0xFFFFFFFFu, ws, o);
                if (lane >= o) ws += t;
            }
            wsum[lane] = ws;
        }
        __syncthreads();
        int c = s_carry;
        int ex = (x - s3) + (w ? wsum[w - 1] : 0) + c;
        int tile_total = wsum[31];
        if (i4 < NI4) {
            int o = i4 * 4;
            g_off[o + 1] = ex + s0;  g_off[o + 2] = ex + s1;
            g_off[o + 3] = ex + s2;  g_off[o + 4] = ex + s3;
            g_cursor[o] = ex;            g_cursor[o + 1] = ex + s0;
            g_cursor[o + 2] = ex + s1;   g_cursor[o + 3] = ex + s2;
        }
        __syncthreads();
        if (tid == 0) s_carry = c + tile_total;
        __syncthreads();
    }
}

__global__ void k_scatter(const int* __restrict__ ei) {
    int i = blockIdx.x * blockDim.x + threadIdx.x;
    if (i < N_EDGES / 4) {
        int4 s = ((const int4*)ei)[i];
        int4 d = ((const int4*)(ei + N_EDGES))[i];
        int p0 = atomicAdd(&g_cursor[s.x], 1);
        int p1 = atomicAdd(&g_cursor[s.y], 1);
        int p2 = atomicAdd(&g_cursor[s.z], 1);
        int p3 = atomicAdd(&g_cursor[s.w], 1);
        g_csr[p0] = d.x; g_csr[p1] = d.y; g_csr[p2] = d.z; g_csr[p3] = d.w;
    }
}

// ====================== fused embed + interact-GEMM(0) =====================
// 50 nodes/block, 400 threads; thread = 2 rows (rl, rl+25) x 4 cols.
// dyn smem: Ws[7744] | Wab[8192] | in_s[6052 pad] | xs[3200]  (100,752 B)
// NOTE: in_s padded 6050->6052 so xs stays 16B-aligned for float4 access.
__global__ __launch_bounds__(400, 2) void k_embed_ab(
    const float* __restrict__ oh, const float* __restrict__ pos,
    const float* __restrict__ embW, const float* __restrict__ embB,
    const float* __restrict__ Wab0) {
    extern __shared__ float smem[];
    float* Ws   = smem;                 // 7744
    float* Wab  = smem + 7744;          // 8192
    float* in_s = smem + 7744 + 8192;   // 6050 used, 6052 reserved
    float* xs   = in_s + 6052;          // 3200 (offset 21988: multiple of 4)
    const int tid = threadIdx.x;
    const int node0 = blockIdx.x * 50;
    {
        float4* d = (float4*)Ws; const float4* s = (const float4*)embW;
        for (int i = tid; i < 7744 / 4; i += 400) d[i] = s[i];
        float4* d2 = (float4*)Wab; const float4* s2 = (const float4*)Wab0;
        for (int i = tid; i < 8192 / 4; i += 400) d2[i] = s2[i];
    }
    for (int i = tid; i < 50 * 118; i += 400) {
        int row = i / 118, k = i % 118;
        in_s[row * 121 + k] = oh[(size_t)(node0 + row) * 118 + k];
    }
    for (int i = tid; i < 50 * 3; i += 400) {
        int row = i / 3, k = i % 3;
        in_s[row * 121 + 118 + k] = pos[(size_t)(node0 + row) * 3 + k];
    }
    __syncthreads();
    const int rl = tid >> 4, cg = tid & 15;   // rows rl and rl+25
    const float4* Ws4 = (const float4*)Ws;
    const float4 eb4 = __ldg((const float4*)(embB) + cg);
    float4 acc0 = eb4, acc1 = eb4;
    #pragma unroll 4
    for (int k = 0; k < 121; k++) {
        float4 w = Ws4[k * 16 + cg];
        float h0 = in_s[rl * 121 + k];
        float h1 = in_s[(rl + 25) * 121 + k];
        acc0.x = fmaf(h0, w.x, acc0.x); acc0.y = fmaf(h0, w.y, acc0.y);
        acc0.z = fmaf(h0, w.z, acc0.z); acc0.w = fmaf(h0, w.w, acc0.w);
        acc1.x = fmaf(h1, w.x, acc1.x); acc1.y = fmaf(h1, w.y, acc1.y);
        acc1.z = fmaf(h1, w.z, acc1.z); acc1.w = fmaf(h1, w.w, acc1.w);
    }
    float4 xv0 = silu4(acc0), xv1 = silu4(acc1);
    {
        int n0 = node0 + rl, n1 = node0 + rl + 25;
        *(float4*)(g_x0 + (size_t)n0 * 64 + cg * 4) = xv0;
        *(float4*)(g_x  + (size_t)n0 * 64 + cg * 4) = xv0;
        *(float4*)(g_x0 + (size_t)n1 * 64 + cg * 4) = xv1;
        *(float4*)(g_x  + (size_t)n1 * 64 + cg * 4) = xv1;
        ((float4*)xs)[rl * 16 + cg] = xv0;
        ((float4*)xs)[(rl + 25) * 16 + cg] = xv1;
    }
    __syncthreads();
    const float4* Wa4 = (const float4*)Wab;
    const float4* Wb4 = Wa4 + 1024;
    float4 a0 = make_float4(0, 0, 0, 0), b0 = a0, a1 = a0, b1 = a0;
    #pragma unroll 4
    for (int k = 0; k < 64; k++) {
        float4 wa = Wa4[k * 16 + cg], wb = Wb4[k * 16 + cg];
        float x0 = xs[rl * 64 + k];
        float x1 = xs[(rl + 25) * 64 + k];
        a0.x = fmaf(x0, wa.x, a0.x); a0.y = fmaf(x0, wa.y, a0.y);
        a0.z = fmaf(x0, wa.z, a0.z); a0.w = fmaf(x0, wa.w, a0.w);
        b0.x = fmaf(x0, wb.x, b0.x); b0.y = fmaf(x0, wb.y, b0.y);
        b0.z = fmaf(x0, wb.z, b0.z); b0.w = fmaf(x0, wb.w, b0.w);
        a1.x = fmaf(x1, wa.x, a1.x); a1.y = fmaf(x1, wa.y, a1.y);
        a1.z = fmaf(x1, wa.z, a1.z); a1.w = fmaf(x1, wa.w, a1.w);
        b1.x = fmaf(x1, wb.x, b1.x); b1.y = fmaf(x1, wb.y, b1.y);
        b1.z = fmaf(x1, wb.z, b1.z); b1.w = fmaf(x1, wb.w, b1.w);
    }
    {
        int n0 = node0 + rl, n1 = node0 + rl + 25;
        *(float4*)(g_a + (size_t)n0 * 64 + cg * 4) = a0;
        *(float4*)(g_b + (size_t)n0 * 64 + cg * 4) = b0;
        *(float4*)(g_a + (size_t)n1 * 64 + cg * 4) = a1;
        *(float4*)(g_b + (size_t)n1 * 64 + cg * 4) = b1;
    }
}

// ========================== CSR edge aggregation ===========================
__global__ __launch_bounds__(512) void k_edge(const float* __restrict__ bias) {
    const int tid = threadIdx.x;
    const int s = blockIdx.x * 32 + (tid >> 4);
    if (s >= N_NODES) return;
    const int c4 = tid & 15;
    float4 a4 = *(const float4*)(g_a + (size_t)s * 64 + c4 * 4);
    a4 = add4(a4, __ldg((const float4*)bias + c4));
    int j = g_off[s];
    const int end = g_off[s + 1];
    float4 acc = make_float4(0, 0, 0, 0);
    for (; j + 3 < end; j += 4) {
        int d0 = __ldg(g_csr + j);
        int d1 = __ldg(g_csr + j + 1);
        int d2 = __ldg(g_csr + j + 2);
        int d3 = __ldg(g_csr + j + 3);
        float4 b0 = *(const float4*)(g_b + (size_t)d0 * 64 + c4 * 4);
        float4 b1 = *(const float4*)(g_b + (size_t)d1 * 64 + c4 * 4);
        float4 b2 = *(const float4*)(g_b + (size_t)d2 * 64 + c4 * 4);
        float4 b3 = *(const float4*)(g_b + (size_t)d3 * 64 + c4 * 4);
        acc = add4(acc, silu4(add4(a4, b0)));
        acc = add4(acc, silu4(add4(a4, b1)));
        acc = add4(acc, silu4(add4(a4, b2)));
        acc = add4(acc, silu4(add4(a4, b3)));
    }
    for (; j < end; ++j) {
        int d = __ldg(g_csr + j);
        float4 b0 = *(const float4*)(g_b + (size_t)d * 64 + c4 * 4);
        acc = add4(acc, silu4(add4(a4, b0)));
    }
    *(float4*)(g_acc + (size_t)s * 64 + c4 * 4) = acc;
}

// =================== fused update(l) + interact-GEMM(l+1) ==================
// 100 nodes/block, 400 threads; thread = 4 rows x 4 cols.
__global__ __launch_bounds__(400, 2) void k_update_ab(
    const float* __restrict__ U, const float* __restrict__ ub,
    const float* __restrict__ Wabn) {
    extern __shared__ float smem[];
    float* Us  = smem;
    float* Wab = smem + 4096;
    float* xs  = smem + 4096 + 8192;
    float* hs  = xs + 6400;
    const int tid = threadIdx.x;
    const int node0 = blockIdx.x * 100;
    {
        float4* d = (float4*)Us; const float4* s = (const float4*)U;
        for (int i = tid; i < 1024; i += 400) d[i] = s[i];
        float4* d2 = (float4*)Wab; const float4* s2 = (const float4*)Wabn;
        for (int i = tid; i < 2048; i += 400) d2[i] = s2[i];
    }
    for (int i = tid; i < 1600; i += 400) {
        int row = i >> 4, c4 = i & 15;
        float4 xv = *(const float4*)(g_x   + (size_t)(node0 + row) * 64 + c4 * 4);
        float4 av = *(const float4*)(g_acc + (size_t)(node0 + row) * 64 + c4 * 4);
        ((float4*)xs)[i] = xv;
        ((float4*)hs)[i] = make_float4(xv.x + 0.25f * av.x, xv.y + 0.25f * av.y,
                                       xv.z + 0.25f * av.z, xv.w + 0.25f * av.w);
    }
    __syncthreads();
    const int rl = tid >> 4, cg = tid & 15;
    const float4* Us4 = (const float4*)Us;
    const float4 ub4 = __ldg((const float4*)(ub) + cg);
    float4 acc0 = ub4, acc1 = ub4, acc2 = ub4, acc3 = ub4;
    #pragma unroll 4
    for (int k = 0; k < 64; k++) {
        float4 w = Us4[k * 16 + cg];
        float h0 = hs[rl * 64 + k];
        float h1 = hs[(rl + 25) * 64 + k];
        float h2 = hs[(rl + 50) * 64 + k];
        float h3 = hs[(rl + 75) * 64 + k];
        acc0.x = fmaf(h0, w.x, acc0.x); acc0.y = fmaf(h0, w.y, acc0.y);
        acc0.z = fmaf(h0, w.z, acc0.z); acc0.w = fmaf(h0, w.w, acc0.w);
        acc1.x = fmaf(h1, w.x, acc1.x); acc1.y = fmaf(h1, w.y, acc1.y);
        acc1.z = fmaf(h1, w.z, acc1.z); acc1.w = fmaf(h1, w.w, acc1.w);
        acc2.x = fmaf(h2, w.x, acc2.x); acc2.y = fmaf(h2, w.y, acc2.y);
        acc2.z = fmaf(h2, w.z, acc2.z); acc2.w = fmaf(h2, w.w, acc2.w);
        acc3.x = fmaf(h3, w.x, acc3.x); acc3.y = fmaf(h3, w.y, acc3.y);
        acc3.z = fmaf(h3, w.z, acc3.z); acc3.w = fmaf(h3, w.w, acc3.w);
    }
    #pragma unroll
    for (int jj = 0; jj < 4; jj++) {
        float4 accv = jj == 0 ? acc0 : jj == 1 ? acc1 : jj == 2 ? acc2 : acc3;
        int row = rl + 25 * jj;
        float4 xo = ((float4*)xs)[row * 16 + cg];
        float4 xn = add4(xo, silu4(accv));
        *(float4*)(g_x + (size_t)(node0 + row) * 64 + cg * 4) = xn;
        ((float4*)xs)[row * 16 + cg] = xn;
    }
    __syncthreads();
    const float4* Wa4 = (const float4*)Wab;
    const float4* Wb4 = Wa4 + 1024;
    float4 a0 = make_float4(0, 0, 0, 0), a1 = a0, a2 = a0, a3 = a0;
    float4 b0 = a0, b1 = a0, b2 = a0, b3 = a0;
    #pragma unroll 2
    for (int k = 0; k < 64; k++) {
        float4 wa = Wa4[k * 16 + cg], wb = Wb4[k * 16 + cg];
        float x0 = xs[rl * 64 + k];
        float x1 = xs[(rl + 25) * 64 + k];
        float x2 = xs[(rl + 50) * 64 + k];
        float x3 = xs[(rl + 75) * 64 + k];
        a0.x = fmaf(x0, wa.x, a0.x); a0.y = fmaf(x0, wa.y, a0.y);
        a0.z = fmaf(x0, wa.z, a0.z); a0.w = fmaf(x0, wa.w, a0.w);
        b0.x = fmaf(x0, wb.x, b0.x); b0.y = fmaf(x0, wb.y, b0.y);
        b0.z = fmaf(x0, wb.z, b0.z); b0.w = fmaf(x0, wb.w, b0.w);
        a1.x = fmaf(x1, wa.x, a1.x); a1.y = fmaf(x1, wa.y, a1.y);
        a1.z = fmaf(x1, wa.z, a1.z); a1.w = fmaf(x1, wa.w, a1.w);
        b1.x = fmaf(x1, wb.x, b1.x); b1.y = fmaf(x1, wb.y, b1.y);
        b1.z = fmaf(x1, wb.z, b1.z); b1.w = fmaf(x1, wb.w, b1.w);
        a2.x = fmaf(x2, wa.x, a2.x); a2.y = fmaf(x2, wa.y, a2.y);
        a2.z = fmaf(x2, wa.z, a2.z); a2.w = fmaf(x2, wa.w, a2.w);
        b2.x = fmaf(x2, wb.x, b2.x); b2.y = fmaf(x2, wb.y, b2.y);
        b2.z = fmaf(x2, wb.z, b2.z); b2.w = fmaf(x2, wb.w, b2.w);
        a3.x = fmaf(x3, wa.x, a3.x); a3.y = fmaf(x3, wa.y, a3.y);
        a3.z = fmaf(x3, wa.z, a3.z); a3.w = fmaf(x3, wa.w, a3.w);
        b3.x = fmaf(x3, wb.x, b3.x); b3.y = fmaf(x3, wb.y, b3.y);
        b3.z = fmaf(x3, wb.z, b3.z); b3.w = fmaf(x3, wb.w, b3.w);
    }
    #pragma unroll
    for (int jj = 0; jj < 4; jj++) {
        float4 av = jj == 0 ? a0 : jj == 1 ? a1 : jj == 2 ? a2 : a3;
        float4 bv = jj == 0 ? b0 : jj == 1 ? b1 : jj == 2 ? b2 : b3;
        int node = node0 + rl + 25 * jj;
        *(float4*)(g_a + (size_t)node * 64 + cg * 4) = av;
        *(float4*)(g_b + (size_t)node * 64 + cg * 4) = bv;
    }
}

// ====================== fused update(3) + output head ======================
// dyn smem: U[4096] | xs[6400] | hs[6400] | Wos[192]
__global__ __launch_bounds__(400, 2) void k_update_out(
    const float* __restrict__ U, const float* __restrict__ ub,
    const float* __restrict__ Wo, const float* __restrict__ bo,
    float* __restrict__ out) {
    extern __shared__ float smem[];
    float* Us  = smem;
    float* xs  = smem + 4096;
    float* hs  = xs + 6400;
    float* Wos = hs + 6400;
    const int tid = threadIdx.x;
    const int node0 = blockIdx.x * 100;
    {
        float4* d = (float4*)Us; const float4* s = (const float4*)U;
        for (int i = tid; i < 1024; i += 400) d[i] = s[i];
        if (tid < 192) Wos[tid] = Wo[tid];
    }
    for (int i = tid; i < 1600; i += 400) {
        int row = i >> 4, c4 = i & 15;
        float4 xv = *(const float4*)(g_x   + (size_t)(node0 + row) * 64 + c4 * 4);
        float4 av = *(const float4*)(g_acc + (size_t)(node0 + row) * 64 + c4 * 4);
        ((float4*)xs)[i] = xv;
        ((float4*)hs)[i] = make_float4(xv.x + 0.25f * av.x, xv.y + 0.25f * av.y,
                                       xv.z + 0.25f * av.z, xv.w + 0.25f * av.w);
    }
    __syncthreads();
    const int rl = tid >> 4, cg = tid & 15;
    const float4* Us4 = (const float4*)Us;
    const float4 ub4 = __ldg((const float4*)(ub) + cg);
    float4 acc0 = ub4, acc1 = ub4, acc2 = ub4, acc3 = ub4;
    #pragma unroll 4
    for (int k = 0; k < 64; k++) {
        float4 w = Us4[k * 16 + cg];
        float h0 = hs[rl * 64 + k];
        float h1 = hs[(rl + 25) * 64 + k];
        float h2 = hs[(rl + 50) * 64 + k];
        float h3 = hs[(rl + 75) * 64 + k];
        acc0.x = fmaf(h0, w.x, acc0.x); acc0.y = fmaf(h0, w.y, acc0.y);
        acc0.z = fmaf(h0, w.z, acc0.z); acc0.w = fmaf(h0, w.w, acc0.w);
        acc1.x = fmaf(h1, w.x, acc1.x); acc1.y = fmaf(h1, w.y, acc1.y);
        acc1.z = fmaf(h1, w.z, acc1.z); acc1.w = fmaf(h1, w.w, acc1.w);
        acc2.x = fmaf(h2, w.x, acc2.x); acc2.y = fmaf(h2, w.y, acc2.y);
        acc2.z = fmaf(h2, w.z, acc2.z); acc2.w = fmaf(h2, w.w, acc2.w);
        acc3.x = fmaf(h3, w.x, acc3.x); acc3.y = fmaf(h3, w.y, acc3.y);
        acc3.z = fmaf(h3, w.z, acc3.z); acc3.w = fmaf(h3, w.w, acc3.w);
    }
    #pragma unroll
    for (int jj = 0; jj < 4; jj++) {
        float4 accv = jj == 0 ? acc0 : jj == 1 ? acc1 : jj == 2 ? acc2 : acc3;
        int row = rl + 25 * jj;
        int node = node0 + row;
        float4 sv = silu4(accv);
        float4 xo = ((float4*)xs)[row * 16 + cg];
        float4 x0v = *(const float4*)(g_x0 + (size_t)node * 64 + cg * 4);
        float4 v = make_float4(x0v.x + xo.x + sv.x, x0v.y + xo.y + sv.y,
                               x0v.z + xo.z + sv.z, x0v.w + xo.w + sv.w);
        const int cb = cg * 4;
        float p0 = v.x * Wos[(cb + 0) * 3 + 0] + v.y * Wos[(cb + 1) * 3 + 0]
                 + v.z * Wos[(cb + 2) * 3 + 0] + v.w * Wos[(cb + 3) * 3 + 0];
        float p1 = v.x * Wos[(cb + 0) * 3 + 1] + v.y * Wos[(cb + 1) * 3 + 1]
                 + v.z * Wos[(cb + 2) * 3 + 1] + v.w * Wos[(cb + 3) * 3 + 1];
        float p2 = v.x * Wos[(cb + 0) * 3 + 2] + v.y * Wos[(cb + 1) * 3 + 2]
                 + v.z * Wos[(cb + 2) * 3 + 2] + v.w * Wos[(cb + 3) * 3 + 2];
        #pragma unroll
        for (int off = 8; off > 0; off >>= 1) {
            p0 += __shfl_down_sync(0xFFFFFFFFu, p0, off, 16);
            p1 += __shfl_down_sync(0xFFFFFFFFu, p1, off, 16);
            p2 += __shfl_down_sync(0xFFFFFFFFu, p2, off, 16);
        }
        if (cg == 0) {
            out[node * 3 + 0] = p0 + __ldg(bo + 0);
            out[node * 3 + 1] = p1 + __ldg(bo + 1);
            out[node * 3 + 2] = p2 + __ldg(bo + 2);
        }
    }
}

// ================================ launcher =================================
extern "C" void kernel_launch(void* const* d_in, const int* in_sizes, int n_in,
                              void* d_out, int out_size) {
    const float* oh   = (const float*)d_in[0];
    const float* pos  = (const float*)d_in[1];
    const int*   ei   = (const int*)d_in[2];
    const float* embW = (const float*)d_in[3];
    const float* embB = (const float*)d_in[4];
    const float* iW   = (const float*)d_in[5];   // [4, 128, 64]
    const float* iB   = (const float*)d_in[6];   // [4, 64]
    const float* uW   = (const float*)d_in[7];   // [4, 64, 64]
    const float* uB   = (const float*)d_in[8];   // [4, 64]
    const float* oW   = (const float*)d_in[9];   // [64, 3]
    const float* oB   = (const float*)d_in[10];  // [3]
    float* out = (float*)d_out;

    static cudaStream_t s2 = nullptr;
    static cudaEvent_t ev_fork = nullptr, ev_join = nullptr;
    static bool attrs_set = false;
    const int EMBED_SMEM  = (7744 + 8192 + 6052 + 3200) * 4;   // 100,752 B
    const int UPDATE_SMEM = (4096 + 8192 + 6400 + 6400) * 4;   // 100,352 B
    const int UOUT_SMEM   = (4096 + 6400 + 6400 + 192) * 4;    // 68,352 B
    if (!attrs_set) {
        cudaStreamCreateWithFlags(&s2, cudaStreamNonBlocking);
        cudaEventCreateWithFlags(&ev_fork, cudaEventDisableTiming);
        cudaEventCreateWithFlags(&ev_join, cudaEventDisableTiming);
        cudaFuncSetAttribute(k_embed_ab,  cudaFuncAttributeMaxDynamicSharedMemorySize, EMBED_SMEM);
        cudaFuncSetAttribute(k_update_ab, cudaFuncAttributeMaxDynamicSharedMemorySize, UPDATE_SMEM);
        cudaFuncSetAttribute(k_update_out,cudaFuncAttributeMaxDynamicSharedMemorySize, UOUT_SMEM);
        attrs_set = true;
    }

    // Fork: CSR build on s2, embed on legacy stream, join before first edge.
    cudaEventRecord(ev_fork, 0);
    cudaStreamWaitEvent(s2, ev_fork, 0);
    k_hist<<<(N_EDGES / 4 + 255) / 256, 256, 0, s2>>>(ei);
    k_scan<<<1, 1024, 0, s2>>>();
    k_scatter<<<(N_EDGES / 4 + 255) / 256, 256, 0, s2>>>(ei);
    cudaEventRecord(ev_join, s2);

    k_embed_ab<<<N_NODES / 50, 400, EMBED_SMEM>>>(oh, pos, embW, embB, iW);
    cudaStreamWaitEvent(0, ev_join, 0);

    for (int l = 0; l < 4; l++) {
        k_edge<<<(N_NODES + 31) / 32, 512>>>(iB + l * 64);
        if (l < 3)
            k_update_ab<<<N_NODES / 100, 400, UPDATE_SMEM>>>(
                uW + (size_t)l * 4096, uB + l * 64, iW + (size_t)(l + 1) * 8192);
        else
            k_update_out<<<N_NODES / 100, 400, UOUT_SMEM>>>(
                uW + (size_t)l * 4096, uB + l * 64, oW, oB, out);
    }
}

// round 12
// speedup vs baseline: 1.3445x; 1.0602x over previous
#include <cuda_runtime.h>
#include <cstdint>

#define N_NODES 50000
#define N_EDGES 800000
#define H 64

// ---------------- scratch (device globals; no allocations) ----------------
__device__ __align__(16) float g_x0 [N_NODES * H];
__device__ __align__(16) float g_x  [N_NODES * H];
__device__ __align__(16) float g_a  [N_NODES * H];
__device__ __align__(16) float g_b  [N_NODES * H];
__device__ __align__(16) float g_acc[N_NODES * H];
__device__ __align__(16) int g_deg[N_NODES];     // static-zero; re-zeroed by k_scan
__device__ int g_off[N_NODES + 1];
__device__ int g_cursor[N_NODES];
__device__ int g_csr[N_EDGES];

// silu(z) = 0.5*z*(1 + tanh(z/2)) -- single MUFU.TANH
__device__ __forceinline__ float silu_f(float z) {
    float t;
    asm("tanh.approx.f32 %0, %1;" : "=f"(t) : "f"(0.5f * z));
    return 0.5f * z * (1.0f + t);
}
__device__ __forceinline__ float4 silu4(float4 z) {
    return make_float4(silu_f(z.x), silu_f(z.y), silu_f(z.z), silu_f(z.w));
}
__device__ __forceinline__ float4 add4(float4 a, float4 b) {
    return make_float4(a.x + b.x, a.y + b.y, a.z + b.z, a.w + b.w);
}

// ============================ CSR construction =============================
__global__ void k_hist(const int* __restrict__ ei) {
    int i = blockIdx.x * blockDim.x + threadIdx.x;
    if (i < N_EDGES / 4) {
        int4 v = ((const int4*)ei)[i];
        atomicAdd(&g_deg[v.x], 1);
        atomicAdd(&g_deg[v.y], 1);
        atomicAdd(&g_deg[v.z], 1);
        atomicAdd(&g_deg[v.w], 1);
    }
}

__global__ __launch_bounds__(1024) void k_scan() {
    __shared__ int wsum[32];
    __shared__ int s_carry;
    const int tid = threadIdx.x, lane = tid & 31, w = tid >> 5;
    if (tid == 0) { g_off[0] = 0; s_carry = 0; }
    __syncthreads();
    const int NI4 = N_NODES / 4;  // 12500
    for (int base = 0; base < NI4; base += 1024) {
        int i4 = base + tid;
        int4 v = make_int4(0, 0, 0, 0);
        if (i4 < NI4) {
            v = ((const int4*)g_deg)[i4];
            ((int4*)g_deg)[i4] = make_int4(0, 0, 0, 0);   // re-zero for next call
        }
        int s0 = v.x, s1 = s0 + v.y, s2 = s1 + v.z, s3 = s2 + v.w;
        int x = s3;
        #pragma unroll
        for (int o = 1; o < 32; o <<= 1) {
            int t = __shfl_up_sync(0xFFFFFFFFu, x, o);
            if (lane >= o) x += t;
        }
        if (lane == 31) wsum[w] = x;
        __syncthreads();
        if (w == 0) {
            int ws = wsum[lane];
            #pragma unroll
            for (int o = 1; o < 32; o <<= 1) {
                int t = __shfl_up_sync(0xFFFFFFFFu, ws, o);
                if (lane >= o) ws += t;
            }
            wsum[lane] = ws;
        }
        __syncthreads();
        int c = s_carry;
        int ex = (x - s3) + (w ? wsum[w - 1] : 0) + c;
        int tile_total = wsum[31];
        if (i4 < NI4) {
            int o = i4 * 4;
            g_off[o + 1] = ex + s0;  g_off[o + 2] = ex + s1;
            g_off[o + 3] = ex + s2;  g_off[o + 4] = ex + s3;
            g_cursor[o] = ex;            g_cursor[o + 1] = ex + s0;
            g_cursor[o + 2] = ex + s1;   g_cursor[o + 3] = ex + s2;
        }
        __syncthreads();
        if (tid == 0) s_carry = c + tile_total;
        __syncthreads();
    }
}

__global__ void k_scatter(const int* __restrict__ ei) {
    int i = blockIdx.x * blockDim.x + threadIdx.x;
    if (i < N_EDGES / 4) {
        int4 s = ((const int4*)ei)[i];
        int4 d = ((const int4*)(ei + N_EDGES))[i];
        int p0 = atomicAdd(&g_cursor[s.x], 1);
        int p1 = atomicAdd(&g_cursor[s.y], 1);
        int p2 = atomicAdd(&g_cursor[s.z], 1);
        int p3 = atomicAdd(&g_cursor[s.w], 1);
        g_csr[p0] = d.x; g_csr[p1] = d.y; g_csr[p2] = d.z; g_csr[p3] = d.w;
    }
}

// ====================== fused embed + interact-GEMM(0) =====================
// 80 nodes/block, 320 threads (20 groups x 16); thread = 4 rows x 4 cols.
// dyn smem: Ws[7744] | buf[9680] (union: in_s 80x121, then Wab 8192) | xs[5120]
// Total 22544 floats = 90,176 B -> 2 blocks/SM.
__global__ __launch_bounds__(320, 2) void k_embed_ab(
    const float* __restrict__ oh, const float* __restrict__ pos,
    const float* __restrict__ embW, const float* __restrict__ embB,
    const float* __restrict__ Wab0) {
    extern __shared__ float smem[];
    float* Ws  = smem;            // 7744
    float* buf = smem + 7744;     // 9680 union region
    float* xs  = smem + 17424;    // 5120 (offset multiple of 4)
    const int tid = threadIdx.x;
    const int node0 = blockIdx.x * 80;
    // stage embW
    {
        float4* d = (float4*)Ws; const float4* s = (const float4*)embW;
        for (int i = tid; i < 1936; i += 320) d[i] = s[i];
    }
    // stage inputs into in_s (= buf), row stride 121
    float* in_s = buf;
    for (int i = tid; i < 80 * 118; i += 320) {
        int row = i / 118, k = i % 118;
        in_s[row * 121 + k] = oh[(size_t)(node0 + row) * 118 + k];
    }
    for (int i = tid; i < 80 * 3; i += 320) {
        int row = i / 3, k = i % 3;
        in_s[row * 121 + 118 + k] = pos[(size_t)(node0 + row) * 3 + k];
    }
    __syncthreads();
    const int g = tid >> 4, cg = tid & 15;   // rows g, g+20, g+40, g+60
    const float4* Ws4 = (const float4*)Ws;
    const float4 eb4 = __ldg((const float4*)(embB) + cg);
    float4 A0 = eb4, A1 = eb4, A2 = eb4, A3 = eb4;
    #pragma unroll 4
    for (int k = 0; k < 121; k++) {
        float4 w = Ws4[k * 16 + cg];
        float h0 = in_s[g * 121 + k];
        float h1 = in_s[(g + 20) * 121 + k];
        float h2 = in_s[(g + 40) * 121 + k];
        float h3 = in_s[(g + 60) * 121 + k];
        A0.x = fmaf(h0, w.x, A0.x); A0.y = fmaf(h0, w.y, A0.y);
        A0.z = fmaf(h0, w.z, A0.z); A0.w = fmaf(h0, w.w, A0.w);
        A1.x = fmaf(h1, w.x, A1.x); A1.y = fmaf(h1, w.y, A1.y);
        A1.z = fmaf(h1, w.z, A1.z); A1.w = fmaf(h1, w.w, A1.w);
        A2.x = fmaf(h2, w.x, A2.x); A2.y = fmaf(h2, w.y, A2.y);
        A2.z = fmaf(h2, w.z, A2.z); A2.w = fmaf(h2, w.w, A2.w);
        A3.x = fmaf(h3, w.x, A3.x); A3.y = fmaf(h3, w.y, A3.y);
        A3.z = fmaf(h3, w.z, A3.z); A3.w = fmaf(h3, w.w, A3.w);
    }
    #pragma unroll
    for (int jj = 0; jj < 4; jj++) {
        float4 av = jj == 0 ? A0 : jj == 1 ? A1 : jj == 2 ? A2 : A3;
        int row = g + 20 * jj;
        int node = node0 + row;
        float4 xv = silu4(av);
        *(float4*)(g_x0 + (size_t)node * 64 + cg * 4) = xv;
        *(float4*)(g_x  + (size_t)node * 64 + cg * 4) = xv;
        ((float4*)xs)[row * 16 + cg] = xv;
    }
    __syncthreads();   // all in_s reads complete before overwriting buf
    // stage Wab into buf
    {
        float4* d = (float4*)buf; const float4* s = (const float4*)Wab0;
        for (int i = tid; i < 2048; i += 320) d[i] = s[i];
    }
    __syncthreads();
    const float4* Wa4 = (const float4*)buf;
    const float4* Wb4 = Wa4 + 1024;
    float4 a0 = make_float4(0, 0, 0, 0), a1 = a0, a2 = a0, a3 = a0;
    float4 b0 = a0, b1 = a0, b2 = a0, b3 = a0;
    #pragma unroll 2
    for (int k = 0; k < 64; k++) {
        float4 wa = Wa4[k * 16 + cg], wb = Wb4[k * 16 + cg];
        float x0 = xs[g * 64 + k];
        float x1 = xs[(g + 20) * 64 + k];
        float x2 = xs[(g + 40) * 64 + k];
        float x3 = xs[(g + 60) * 64 + k];
        a0.x = fmaf(x0, wa.x, a0.x); a0.y = fmaf(x0, wa.y, a0.y);
        a0.z = fmaf(x0, wa.z, a0.z); a0.w = fmaf(x0, wa.w, a0.w);
        b0.x = fmaf(x0, wb.x, b0.x); b0.y = fmaf(x0, wb.y, b0.y);
        b0.z = fmaf(x0, wb.z, b0.z); b0.w = fmaf(x0, wb.w, b0.w);
        a1.x = fmaf(x1, wa.x, a1.x); a1.y = fmaf(x1, wa.y, a1.y);
        a1.z = fmaf(x1, wa.z, a1.z); a1.w = fmaf(x1, wa.w, a1.w);
        b1.x = fmaf(x1, wb.x, b1.x); b1.y = fmaf(x1, wb.y, b1.y);
        b1.z = fmaf(x1, wb.z, b1.z); b1.w = fmaf(x1, wb.w, b1.w);
        a2.x = fmaf(x2, wa.x, a2.x); a2.y = fmaf(x2, wa.y, a2.y);
        a2.z = fmaf(x2, wa.z, a2.z); a2.w = fmaf(x2, wa.w, a2.w);
        b2.x = fmaf(x2, wb.x, b2.x); b2.y = fmaf(x2, wb.y, b2.y);
        b2.z = fmaf(x2, wb.z, b2.z); b2.w = fmaf(x2, wb.w, b2.w);
        a3.x = fmaf(x3, wa.x, a3.x); a3.y = fmaf(x3, wa.y, a3.y);
        a3.z = fmaf(x3, wa.z, a3.z); a3.w = fmaf(x3, wa.w, a3.w);
        b3.x = fmaf(x3, wb.x, b3.x); b3.y = fmaf(x3, wb.y, b3.y);
        b3.z = fmaf(x3, wb.z, b3.z); b3.w = fmaf(x3, wb.w, b3.w);
    }
    #pragma unroll
    for (int jj = 0; jj < 4; jj++) {
        float4 av = jj == 0 ? a0 : jj == 1 ? a1 : jj == 2 ? a2 : a3;
        float4 bv = jj == 0 ? b0 : jj == 1 ? b1 : jj == 2 ? b2 : b3;
        int node = node0 + g + 20 * jj;
        *(float4*)(g_a + (size_t)node * 64 + cg * 4) = av;
        *(float4*)(g_b + (size_t)node * 64 + cg * 4) = bv;
    }
}

// ========================== CSR edge aggregation ===========================
__global__ __launch_bounds__(512) void k_edge(const float* __restrict__ bias) {
    const int tid = threadIdx.x;
    const int s = blockIdx.x * 32 + (tid >> 4);
    if (s >= N_NODES) return;
    const int c4 = tid & 15;
    float4 a4 = *(const float4*)(g_a + (size_t)s * 64 + c4 * 4);
    a4 = add4(a4, __ldg((const float4*)bias + c4));
    int j = g_off[s];
    const int end = g_off[s + 1];
    float4 acc = make_float4(0, 0, 0, 0);
    for (; j + 3 < end; j += 4) {
        int d0 = __ldg(g_csr + j);
        int d1 = __ldg(g_csr + j + 1);
        int d2 = __ldg(g_csr + j + 2);
        int d3 = __ldg(g_csr + j + 3);
        float4 b0 = *(const float4*)(g_b + (size_t)d0 * 64 + c4 * 4);
        float4 b1 = *(const float4*)(g_b + (size_t)d1 * 64 + c4 * 4);
        float4 b2 = *(const float4*)(g_b + (size_t)d2 * 64 + c4 * 4);
        float4 b3 = *(const float4*)(g_b + (size_t)d3 * 64 + c4 * 4);
        acc = add4(acc, silu4(add4(a4, b0)));
        acc = add4(acc, silu4(add4(a4, b1)));
        acc = add4(acc, silu4(add4(a4, b2)));
        acc = add4(acc, silu4(add4(a4, b3)));
    }
    for (; j < end; ++j) {
        int d = __ldg(g_csr + j);
        float4 b0 = *(const float4*)(g_b + (size_t)d * 64 + c4 * 4);
        acc = add4(acc, silu4(add4(a4, b0)));
    }
    *(float4*)(g_acc + (size_t)s * 64 + c4 * 4) = acc;
}

// =================== fused update(l) + interact-GEMM(l+1) ==================
// 100 nodes/block, 400 threads; thread = 4 rows x 4 cols.
__global__ __launch_bounds__(400, 2) void k_update_ab(
    const float* __restrict__ U, const float* __restrict__ ub,
    const float* __restrict__ Wabn) {
    extern __shared__ float smem[];
    float* Us  = smem;
    float* Wab = smem + 4096;
    float* xs  = smem + 4096 + 8192;
    float* hs  = xs + 6400;
    const int tid = threadIdx.x;
    const int node0 = blockIdx.x * 100;
    {
        float4* d = (float4*)Us; const float4* s = (const float4*)U;
        for (int i = tid; i < 1024; i += 400) d[i] = s[i];
        float4* d2 = (float4*)Wab; const float4* s2 = (const float4*)Wabn;
        for (int i = tid; i < 2048; i += 400) d2[i] = s2[i];
    }
    for (int i = tid; i < 1600; i += 400) {
        int row = i >> 4, c4 = i & 15;
        float4 xv = *(const float4*)(g_x   + (size_t)(node0 + row) * 64 + c4 * 4);
        float4 av = *(const float4*)(g_acc + (size_t)(node0 + row) * 64 + c4 * 4);
        ((float4*)xs)[i] = xv;
        ((float4*)hs)[i] = make_float4(xv.x + 0.25f * av.x, xv.y + 0.25f * av.y,
                                       xv.z + 0.25f * av.z, xv.w + 0.25f * av.w);
    }
    __syncthreads();
    const int rl = tid >> 4, cg = tid & 15;
    const float4* Us4 = (const float4*)Us;
    const float4 ub4 = __ldg((const float4*)(ub) + cg);
    float4 acc0 = ub4, acc1 = ub4, acc2 = ub4, acc3 = ub4;
    #pragma unroll 4
    for (int k = 0; k < 64; k++) {
        float4 w = Us4[k * 16 + cg];
        float h0 = hs[rl * 64 + k];
        float h1 = hs[(rl + 25) * 64 + k];
        float h2 = hs[(rl + 50) * 64 + k];
        float h3 = hs[(rl + 75) * 64 + k];
        acc0.x = fmaf(h0, w.x, acc0.x); acc0.y = fmaf(h0, w.y, acc0.y);
        acc0.z = fmaf(h0, w.z, acc0.z); acc0.w = fmaf(h0, w.w, acc0.w);
        acc1.x = fmaf(h1, w.x, acc1.x); acc1.y = fmaf(h1, w.y, acc1.y);
        acc1.z = fmaf(h1, w.z, acc1.z); acc1.w = fmaf(h1, w.w, acc1.w);
        acc2.x = fmaf(h2, w.x, acc2.x); acc2.y = fmaf(h2, w.y, acc2.y);
        acc2.z = fmaf(h2, w.z, acc2.z); acc2.w = fmaf(h2, w.w, acc2.w);
        acc3.x = fmaf(h3, w.x, acc3.x); acc3.y = fmaf(h3, w.y, acc3.y);
        acc3.z = fmaf(h3, w.z, acc3.z); acc3.w = fmaf(h3, w.w, acc3.w);
    }
    #pragma unroll
    for (int jj = 0; jj < 4; jj++) {
        float4 accv = jj == 0 ? acc0 : jj == 1 ? acc1 : jj == 2 ? acc2 : acc3;
        int row = rl + 25 * jj;
        float4 xo = ((float4*)xs)[row * 16 + cg];
        float4 xn = add4(xo, silu4(accv));
        *(float4*)(g_x + (size_t)(node0 + row) * 64 + cg * 4) = xn;
        ((float4*)xs)[row * 16 + cg] = xn;
    }
    __syncthreads();
    const float4* Wa4 = (const float4*)Wab;
    const float4* Wb4 = Wa4 + 1024;
    float4 a0 = make_float4(0, 0, 0, 0), a1 = a0, a2 = a0, a3 = a0;
    float4 b0 = a0, b1 = a0, b2 = a0, b3 = a0;
    #pragma unroll 2
    for (int k = 0; k < 64; k++) {
        float4 wa = Wa4[k * 16 + cg], wb = Wb4[k * 16 + cg];
        float x0 = xs[rl * 64 + k];
        float x1 = xs[(rl + 25) * 64 + k];
        float x2 = xs[(rl + 50) * 64 + k];
        float x3 = xs[(rl + 75) * 64 + k];
        a0.x = fmaf(x0, wa.x, a0.x); a0.y = fmaf(x0, wa.y, a0.y);
        a0.z = fmaf(x0, wa.z, a0.z); a0.w = fmaf(x0, wa.w, a0.w);
        b0.x = fmaf(x0, wb.x, b0.x); b0.y = fmaf(x0, wb.y, b0.y);
        b0.z = fmaf(x0, wb.z, b0.z); b0.w = fmaf(x0, wb.w, b0.w);
        a1.x = fmaf(x1, wa.x, a1.x); a1.y = fmaf(x1, wa.y, a1.y);
        a1.z = fmaf(x1, wa.z, a1.z); a1.w = fmaf(x1, wa.w, a1.w);
        b1.x = fmaf(x1, wb.x, b1.x); b1.y = fmaf(x1, wb.y, b1.y);
        b1.z = fmaf(x1, wb.z, b1.z); b1.w = fmaf(x1, wb.w, b1.w);
        a2.x = fmaf(x2, wa.x, a2.x); a2.y = fmaf(x2, wa.y, a2.y);
        a2.z = fmaf(x2, wa.z, a2.z); a2.w = fmaf(x2, wa.w, a2.w);
        b2.x = fmaf(x2, wb.x, b2.x); b2.y = fmaf(x2, wb.y, b2.y);
        b2.z = fmaf(x2, wb.z, b2.z); b2.w = fmaf(x2, wb.w, b2.w);
        a3.x = fmaf(x3, wa.x, a3.x); a3.y = fmaf(x3, wa.y, a3.y);
        a3.z = fmaf(x3, wa.z, a3.z); a3.w = fmaf(x3, wa.w, a3.w);
        b3.x = fmaf(x3, wb.x, b3.x); b3.y = fmaf(x3, wb.y, b3.y);
        b3.z = fmaf(x3, wb.z, b3.z); b3.w = fmaf(x3, wb.w, b3.w);
    }
    #pragma unroll
    for (int jj = 0; jj < 4; jj++) {
        float4 av = jj == 0 ? a0 : jj == 1 ? a1 : jj == 2 ? a2 : a3;
        float4 bv = jj == 0 ? b0 : jj == 1 ? b1 : jj == 2 ? b2 : b3;
        int node = node0 + rl + 25 * jj;
        *(float4*)(g_a + (size_t)node * 64 + cg * 4) = av;
        *(float4*)(g_b + (size_t)node * 64 + cg * 4) = bv;
    }
}

// ====================== fused update(3) + output head ======================
// dyn smem: U[4096] | xs[6400] | hs[6400] | Wos[192]
__global__ __launch_bounds__(400, 2) void k_update_out(
    const float* __restrict__ U, const float* __restrict__ ub,
    const float* __restrict__ Wo, const float* __restrict__ bo,
    float* __restrict__ out) {
    extern __shared__ float smem[];
    float* Us  = smem;
    float* xs  = smem + 4096;
    float* hs  = xs + 6400;
    float* Wos = hs + 6400;
    const int tid = threadIdx.x;
    const int node0 = blockIdx.x * 100;
    {
        float4* d = (float4*)Us; const float4* s = (const float4*)U;
        for (int i = tid; i < 1024; i += 400) d[i] = s[i];
        if (tid < 192) Wos[tid] = Wo[tid];
    }
    for (int i = tid; i < 1600; i += 400) {
        int row = i >> 4, c4 = i & 15;
        float4 xv = *(const float4*)(g_x   + (size_t)(node0 + row) * 64 + c4 * 4);
        float4 av = *(const float4*)(g_acc + (size_t)(node0 + row) * 64 + c4 * 4);
        ((float4*)xs)[i] = xv;
        ((float4*)hs)[i] = make_float4(xv.x + 0.25f * av.x, xv.y + 0.25f * av.y,
                                       xv.z + 0.25f * av.z, xv.w + 0.25f * av.w);
    }
    __syncthreads();
    const int rl = tid >> 4, cg = tid & 15;
    const float4* Us4 = (const float4*)Us;
    const float4 ub4 = __ldg((const float4*)(ub) + cg);
    float4 acc0 = ub4, acc1 = ub4, acc2 = ub4, acc3 = ub4;
    #pragma unroll 4
    for (int k = 0; k < 64; k++) {
        float4 w = Us4[k * 16 + cg];
        float h0 = hs[rl * 64 + k];
        float h1 = hs[(rl + 25) * 64 + k];
        float h2 = hs[(rl + 50) * 64 + k];
        float h3 = hs[(rl + 75) * 64 + k];
        acc0.x = fmaf(h0, w.x, acc0.x); acc0.y = fmaf(h0, w.y, acc0.y);
        acc0.z = fmaf(h0, w.z, acc0.z); acc0.w = fmaf(h0, w.w, acc0.w);
        acc1.x = fmaf(h1, w.x, acc1.x); acc1.y = fmaf(h1, w.y, acc1.y);
        acc1.z = fmaf(h1, w.z, acc1.z); acc1.w = fmaf(h1, w.w, acc1.w);
        acc2.x = fmaf(h2, w.x, acc2.x); acc2.y = fmaf(h2, w.y, acc2.y);
        acc2.z = fmaf(h2, w.z, acc2.z); acc2.w = fmaf(h2, w.w, acc2.w);
        acc3.x = fmaf(h3, w.x, acc3.x); acc3.y = fmaf(h3, w.y, acc3.y);
        acc3.z = fmaf(h3, w.z, acc3.z); acc3.w = fmaf(h3, w.w, acc3.w);
    }
    #pragma unroll
    for (int jj = 0; jj < 4; jj++) {
        float4 accv = jj == 0 ? acc0 : jj == 1 ? acc1 : jj == 2 ? acc2 : acc3;
        int row = rl + 25 * jj;
        int node = node0 + row;
        float4 sv = silu4(accv);
        float4 xo = ((float4*)xs)[row * 16 + cg];
        float4 x0v = *(const float4*)(g_x0 + (size_t)node * 64 + cg * 4);
        float4 v = make_float4(x0v.x + xo.x + sv.x, x0v.y + xo.y + sv.y,
                               x0v.z + xo.z + sv.z, x0v.w + xo.w + sv.w);
        const int cb = cg * 4;
        float p0 = v.x * Wos[(cb + 0) * 3 + 0] + v.y * Wos[(cb + 1) * 3 + 0]
                 + v.z * Wos[(cb + 2) * 3 + 0] + v.w * Wos[(cb + 3) * 3 + 0];
        float p1 = v.x * Wos[(cb + 0) * 3 + 1] + v.y * Wos[(cb + 1) * 3 + 1]
                 + v.z * Wos[(cb + 2) * 3 + 1] + v.w * Wos[(cb + 3) * 3 + 1];
        float p2 = v.x * Wos[(cb + 0) * 3 + 2] + v.y * Wos[(cb + 1) * 3 + 2]
                 + v.z * Wos[(cb + 2) * 3 + 2] + v.w * Wos[(cb + 3) * 3 + 2];
        #pragma unroll
        for (int off = 8; off > 0; off >>= 1) {
            p0 += __shfl_down_sync(0xFFFFFFFFu, p0, off, 16);
            p1 += __shfl_down_sync(0xFFFFFFFFu, p1, off, 16);
            p2 += __shfl_down_sync(0xFFFFFFFFu, p2, off, 16);
        }
        if (cg == 0) {
            out[node * 3 + 0] = p0 + __ldg(bo + 0);
            out[node * 3 + 1] = p1 + __ldg(bo + 1);
            out[node * 3 + 2] = p2 + __ldg(bo + 2);
        }
    }
}

// ================================ launcher =================================
extern "C" void kernel_launch(void* const* d_in, const int* in_sizes, int n_in,
                              void* d_out, int out_size) {
    const float* oh   = (const float*)d_in[0];
    const float* pos  = (const float*)d_in[1];
    const int*   ei   = (const int*)d_in[2];
    const float* embW = (const float*)d_in[3];
    const float* embB = (const float*)d_in[4];
    const float* iW   = (const float*)d_in[5];   // [4, 128, 64]
    const float* iB   = (const float*)d_in[6];   // [4, 64]
    const float* uW   = (const float*)d_in[7];   // [4, 64, 64]
    const float* uB   = (const float*)d_in[8];   // [4, 64]
    const float* oW   = (const float*)d_in[9];   // [64, 3]
    const float* oB   = (const float*)d_in[10];  // [3]
    float* out = (float*)d_out;

    static cudaStream_t s2 = nullptr;
    static cudaEvent_t ev_fork = nullptr, ev_join = nullptr;
    static bool attrs_set = false;
    const int EMBED_SMEM  = (7744 + 9680 + 5120) * 4;          // 90,176 B
    const int UPDATE_SMEM = (4096 + 8192 + 6400 + 6400) * 4;   // 100,352 B
    const int UOUT_SMEM   = (4096 + 6400 + 6400 + 192) * 4;    // 68,352 B
    if (!attrs_set) {
        cudaStreamCreateWithFlags(&s2, cudaStreamNonBlocking);
        cudaEventCreateWithFlags(&ev_fork, cudaEventDisableTiming);
        cudaEventCreateWithFlags(&ev_join, cudaEventDisableTiming);
        cudaFuncSetAttribute(k_embed_ab,  cudaFuncAttributeMaxDynamicSharedMemorySize, EMBED_SMEM);
        cudaFuncSetAttribute(k_update_ab, cudaFuncAttributeMaxDynamicSharedMemorySize, UPDATE_SMEM);
        cudaFuncSetAttribute(k_update_out,cudaFuncAttributeMaxDynamicSharedMemorySize, UOUT_SMEM);
        attrs_set = true;
    }

    // Fork: CSR build on s2, embed on legacy stream, join before first edge.
    cudaEventRecord(ev_fork, 0);
    cudaStreamWaitEvent(s2, ev_fork, 0);
    k_hist<<<(N_EDGES / 4 + 255) / 256, 256, 0, s2>>>(ei);
    k_scan<<<1, 1024, 0, s2>>>();
    k_scatter<<<(N_EDGES / 4 + 255) / 256, 256, 0, s2>>>(ei);
    cudaEventRecord(ev_join, s2);

    k_embed_ab<<<N_NODES / 80, 320, EMBED_SMEM>>>(oh, pos, embW, embB, iW);
    cudaStreamWaitEvent(0, ev_join, 0);

    for (int l = 0; l < 4; l++) {
        k_edge<<<(N_NODES + 31) / 32, 512>>>(iB + l * 64);
        if (l < 3)
            k_update_ab<<<N_NODES / 100, 400, UPDATE_SMEM>>>(
                uW + (size_t)l * 4096, uB + l * 64, iW + (size_t)(l + 1) * 8192);
        else
            k_update_out<<<N_NODES / 100, 400, UOUT_SMEM>>>(
                uW + (size_t)l * 4096, uB + l * 64, oW, oB, out);
    }
}

// round 14
// speedup vs baseline: 1.3505x; 1.0044x over previous
#include <cuda_runtime.h>
#include <cstdint>

#define N_NODES 50000
#define N_EDGES 800000
#define H 64

// ---------------- scratch (device globals; no allocations) ----------------
__device__ __align__(16) float g_x0 [N_NODES * H];
__device__ __align__(16) float g_x  [N_NODES * H];
__device__ __align__(16) float g_a  [N_NODES * H];
__device__ __align__(16) float g_b  [N_NODES * H];
__device__ __align__(16) float g_acc[N_NODES * H];
__device__ __align__(16) int g_deg[N_NODES];     // static-zero; re-zeroed by k_scan
__device__ int g_off[N_NODES + 1];
__device__ int g_cursor[N_NODES];
__device__ int g_csr[N_EDGES];

// silu(z) = 0.5*z*(1 + tanh(z/2)) -- single MUFU.TANH
__device__ __forceinline__ float silu_f(float z) {
    float t;
    asm("tanh.approx.f32 %0, %1;" : "=f"(t) : "f"(0.5f * z));
    return 0.5f * z * (1.0f + t);
}
__device__ __forceinline__ float4 silu4(float4 z) {
    return make_float4(silu_f(z.x), silu_f(z.y), silu_f(z.z), silu_f(z.w));
}
__device__ __forceinline__ float4 add4(float4 a, float4 b) {
    return make_float4(a.x + b.x, a.y + b.y, a.z + b.z, a.w + b.w);
}

// A_ (float4) += h_ (scalar) * w_ (float4)   [hygienic param names]
#define FMA4(A_, h_, w_) \
    A_.x = fmaf(h_, w_.x, A_.x); A_.y = fmaf(h_, w_.y, A_.y); \
    A_.z = fmaf(h_, w_.z, A_.z); A_.w = fmaf(h_, w_.w, A_.w);

// ============================ CSR construction =============================
__global__ void k_hist(const int* __restrict__ ei) {
    int i = blockIdx.x * blockDim.x + threadIdx.x;
    if (i < N_EDGES / 4) {
        int4 v = ((const int4*)ei)[i];
        atomicAdd(&g_deg[v.x], 1);
        atomicAdd(&g_deg[v.y], 1);
        atomicAdd(&g_deg[v.z], 1);
        atomicAdd(&g_deg[v.w], 1);
    }
}

__global__ __launch_bounds__(1024) void k_scan() {
    __shared__ int wsum[32];
    __shared__ int s_carry;
    const int tid = threadIdx.x, lane = tid & 31, w = tid >> 5;
    if (tid == 0) { g_off[0] = 0; s_carry = 0; }
    __syncthreads();
    const int NI4 = N_NODES / 4;  // 12500
    for (int base = 0; base < NI4; base += 1024) {
        int i4 = base + tid;
        int4 v = make_int4(0, 0, 0, 0);
        if (i4 < NI4) {
            v = ((const int4*)g_deg)[i4];
            ((int4*)g_deg)[i4] = make_int4(0, 0, 0, 0);   // re-zero for next call
        }
        int s0 = v.x, s1 = s0 + v.y, s2 = s1 + v.z, s3 = s2 + v.w;
        int x = s3;
        #pragma unroll
        for (int o = 1; o < 32; o <<= 1) {
            int t = __shfl_up_sync(0xFFFFFFFFu, x, o);
            if (lane >= o) x += t;
        }
        if (lane == 31) wsum[w] = x;
        __syncthreads();
        if (w == 0) {
            int ws = wsum[lane];
            #pragma unroll
            for (int o = 1; o < 32; o <<= 1) {
                int t = __shfl_up_sync(0xFFFFFFFFu, ws, o);
                if (lane >= o) ws += t;
            }
            wsum[lane] = ws;
        }
        __syncthreads();
        int c = s_carry;
        int ex = (x - s3) + (w ? wsum[w - 1] : 0) + c;
        int tile_total = wsum[31];
        if (i4 < NI4) {
            int o = i4 * 4;
            g_off[o + 1] = ex + s0;  g_off[o + 2] = ex + s1;
            g_off[o + 3] = ex + s2;  g_off[o + 4] = ex + s3;
            g_cursor[o] = ex;            g_cursor[o + 1] = ex + s0;
            g_cursor[o + 2] = ex + s1;   g_cursor[o + 3] = ex + s2;
        }
        __syncthreads();
        if (tid == 0) s_carry = c + tile_total;
        __syncthreads();
    }
}

__global__ void k_scatter(const int* __restrict__ ei) {
    int i = blockIdx.x * blockDim.x + threadIdx.x;
    if (i < N_EDGES / 4) {
        int4 s = ((const int4*)ei)[i];
        int4 d = ((const int4*)(ei + N_EDGES))[i];
        int p0 = atomicAdd(&g_cursor[s.x], 1);
        int p1 = atomicAdd(&g_cursor[s.y], 1);
        int p2 = atomicAdd(&g_cursor[s.z], 1);
        int p3 = atomicAdd(&g_cursor[s.w], 1);
        g_csr[p0] = d.x; g_csr[p1] = d.y; g_csr[p2] = d.z; g_csr[p3] = d.w;
    }
}

// ====================== fused embed + interact-GEMM(0) =====================
// 80 nodes/block, 320 threads (20 groups x 16); thread = 4 rows x 4 cols.
// K vectorized: h loaded as float4 spanning 4 k values (in_s row stride 124).
// dyn smem: Ws[7936 = 124*64] | buf[9920] (union: in_s 80x124, then Wab 8192)
//           | xs[5120].  Total 22976 floats = 91,904 B -> 2 blocks/SM.
__global__ __launch_bounds__(320, 2) void k_embed_ab(
    const float* __restrict__ oh, const float* __restrict__ pos,
    const float* __restrict__ embW, const float* __restrict__ embB,
    const float* __restrict__ Wab0) {
    extern __shared__ float smem[];
    float* Ws  = smem;            // 7936 (rows 121-123 zeroed)
    float* buf = smem + 7936;     // 9920 union region
    float* xs  = smem + 17856;    // 5120
    const int tid = threadIdx.x;
    const int node0 = blockIdx.x * 80;
    // stage embW (7744 floats) + zero pad rows 121..123 (192 floats)
    {
        float4* d = (float4*)Ws; const float4* s = (const float4*)embW;
        for (int i = tid; i < 1936; i += 320) d[i] = s[i];
        for (int i = tid; i < 48; i += 320) d[1936 + i] = make_float4(0, 0, 0, 0);
    }
    // stage inputs into in_s (= buf), row stride 124; zero pad cols 121..123
    float* in_s = buf;
    for (int i = tid; i < 80 * 118; i += 320) {
        int row = i / 118, k = i % 118;
        in_s[row * 124 + k] = oh[(size_t)(node0 + row) * 118 + k];
    }
    for (int i = tid; i < 80 * 3; i += 320) {
        int row = i / 3, k = i % 3;
        in_s[row * 124 + 118 + k] = pos[(size_t)(node0 + row) * 3 + k];
        in_s[row * 124 + 121 + k] = 0.0f;
    }
    __syncthreads();
    const int g = tid >> 4, cg = tid & 15;   // rows g, g+20, g+40, g+60
    const float4* Ws4 = (const float4*)Ws;
    const float4 eb4 = __ldg((const float4*)(embB) + cg);
    float4 A0 = eb4, A1 = eb4, A2 = eb4, A3 = eb4;
    #pragma unroll 2
    for (int k0 = 0; k0 < 124; k0 += 4) {
        float4 hA = *(const float4*)(in_s + g * 124 + k0);
        float4 hB = *(const float4*)(in_s + (g + 20) * 124 + k0);
        float4 hC = *(const float4*)(in_s + (g + 40) * 124 + k0);
        float4 hD = *(const float4*)(in_s + (g + 60) * 124 + k0);
        float4 u0 = Ws4[(k0 + 0) * 16 + cg];
        float4 u1 = Ws4[(k0 + 1) * 16 + cg];
        float4 u2 = Ws4[(k0 + 2) * 16 + cg];
        float4 u3 = Ws4[(k0 + 3) * 16 + cg];
        FMA4(A0, hA.x, u0) FMA4(A0, hA.y, u1) FMA4(A0, hA.z, u2) FMA4(A0, hA.w, u3)
        FMA4(A1, hB.x, u0) FMA4(A1, hB.y, u1) FMA4(A1, hB.z, u2) FMA4(A1, hB.w, u3)
        FMA4(A2, hC.x, u0) FMA4(A2, hC.y, u1) FMA4(A2, hC.z, u2) FMA4(A2, hC.w, u3)
        FMA4(A3, hD.x, u0) FMA4(A3, hD.y, u1) FMA4(A3, hD.z, u2) FMA4(A3, hD.w, u3)
    }
    #pragma unroll
    for (int jj = 0; jj < 4; jj++) {
        float4 av = jj == 0 ? A0 : jj == 1 ? A1 : jj == 2 ? A2 : A3;
        int row = g + 20 * jj;
        int node = node0 + row;
        float4 xv = silu4(av);
        *(float4*)(g_x0 + (size_t)node * 64 + cg * 4) = xv;
        *(float4*)(g_x  + (size_t)node * 64 + cg * 4) = xv;
        ((float4*)xs)[row * 16 + cg] = xv;
    }
    __syncthreads();   // all in_s reads complete before overwriting buf
    // stage Wab into buf
    {
        float4* d = (float4*)buf; const float4* s = (const float4*)Wab0;
        for (int i = tid; i < 2048; i += 320) d[i] = s[i];
    }
    __syncthreads();
    const float4* Wa4 = (const float4*)buf;
    const float4* Wb4 = Wa4 + 1024;
    float4 a0 = make_float4(0, 0, 0, 0), a1 = a0, a2 = a0, a3 = a0;
    float4 b0 = a0, b1 = a0, b2 = a0, b3 = a0;
    #pragma unroll 2
    for (int k0 = 0; k0 < 64; k0 += 2) {
        float2 xA = *(const float2*)(xs + g * 64 + k0);
        float2 xB = *(const float2*)(xs + (g + 20) * 64 + k0);
        float2 xC = *(const float2*)(xs + (g + 40) * 64 + k0);
        float2 xD = *(const float2*)(xs + (g + 60) * 64 + k0);
        float4 ua0 = Wa4[k0 * 16 + cg], ua1 = Wa4[(k0 + 1) * 16 + cg];
        float4 ub0 = Wb4[k0 * 16 + cg], ub1 = Wb4[(k0 + 1) * 16 + cg];
        FMA4(a0, xA.x, ua0) FMA4(a0, xA.y, ua1)
        FMA4(b0, xA.x, ub0) FMA4(b0, xA.y, ub1)
        FMA4(a1, xB.x, ua0) FMA4(a1, xB.y, ua1)
        FMA4(b1, xB.x, ub0) FMA4(b1, xB.y, ub1)
        FMA4(a2, xC.x, ua0) FMA4(a2, xC.y, ua1)
        FMA4(b2, xC.x, ub0) FMA4(b2, xC.y, ub1)
        FMA4(a3, xD.x, ua0) FMA4(a3, xD.y, ua1)
        FMA4(b3, xD.x, ub0) FMA4(b3, xD.y, ub1)
    }
    #pragma unroll
    for (int jj = 0; jj < 4; jj++) {
        float4 av = jj == 0 ? a0 : jj == 1 ? a1 : jj == 2 ? a2 : a3;
        float4 bv = jj == 0 ? b0 : jj == 1 ? b1 : jj == 2 ? b2 : b3;
        int node = node0 + g + 20 * jj;
        *(float4*)(g_a + (size_t)node * 64 + cg * 4) = av;
        *(float4*)(g_b + (size_t)node * 64 + cg * 4) = bv;
    }
}

// ========================== CSR edge aggregation ===========================
__global__ __launch_bounds__(512) void k_edge(const float* __restrict__ bias) {
    const int tid = threadIdx.x;
    const int s = blockIdx.x * 32 + (tid >> 4);
    if (s >= N_NODES) return;
    const int c4 = tid & 15;
    float4 a4 = *(const float4*)(g_a + (size_t)s * 64 + c4 * 4);
    a4 = add4(a4, __ldg((const float4*)bias + c4));
    int j = g_off[s];
    const int end = g_off[s + 1];
    float4 acc = make_float4(0, 0, 0, 0);
    for (; j + 3 < end; j += 4) {
        int d0 = __ldg(g_csr + j);
        int d1 = __ldg(g_csr + j + 1);
        int d2 = __ldg(g_csr + j + 2);
        int d3 = __ldg(g_csr + j + 3);
        float4 b0 = *(const float4*)(g_b + (size_t)d0 * 64 + c4 * 4);
        float4 b1 = *(const float4*)(g_b + (size_t)d1 * 64 + c4 * 4);
        float4 b2 = *(const float4*)(g_b + (size_t)d2 * 64 + c4 * 4);
        float4 b3 = *(const float4*)(g_b + (size_t)d3 * 64 + c4 * 4);
        acc = add4(acc, silu4(add4(a4, b0)));
        acc = add4(acc, silu4(add4(a4, b1)));
        acc = add4(acc, silu4(add4(a4, b2)));
        acc = add4(acc, silu4(add4(a4, b3)));
    }
    for (; j < end; ++j) {
        int d = __ldg(g_csr + j);
        float4 b0 = *(const float4*)(g_b + (size_t)d * 64 + c4 * 4);
        acc = add4(acc, silu4(add4(a4, b0)));
    }
    *(float4*)(g_acc + (size_t)s * 64 + c4 * 4) = acc;
}

// =================== fused update(l) + interact-GEMM(l+1) ==================
// 100 nodes/block, 400 threads; thread = 4 rows x 4 cols; k vectorized.
__global__ __launch_bounds__(400, 2) void k_update_ab(
    const float* __restrict__ U, const float* __restrict__ ub,
    const float* __restrict__ Wabn) {
    extern __shared__ float smem[];
    float* Us  = smem;
    float* Wab = smem + 4096;
    float* xs  = smem + 4096 + 8192;
    float* hs  = xs + 6400;
    const int tid = threadIdx.x;
    const int node0 = blockIdx.x * 100;
    {
        float4* d = (float4*)Us; const float4* s = (const float4*)U;
        for (int i = tid; i < 1024; i += 400) d[i] = s[i];
        float4* d2 = (float4*)Wab; const float4* s2 = (const float4*)Wabn;
        for (int i = tid; i < 2048; i += 400) d2[i] = s2[i];
    }
    for (int i = tid; i < 1600; i += 400) {
        int row = i >> 4, c4 = i & 15;
        float4 xv = *(const float4*)(g_x   + (size_t)(node0 + row) * 64 + c4 * 4);
        float4 av = *(const float4*)(g_acc + (size_t)(node0 + row) * 64 + c4 * 4);
        ((float4*)xs)[i] = xv;
        ((float4*)hs)[i] = make_float4(xv.x + 0.25f * av.x, xv.y + 0.25f * av.y,
                                       xv.z + 0.25f * av.z, xv.w + 0.25f * av.w);
    }
    __syncthreads();
    const int rl = tid >> 4, cg = tid & 15;
    const float4* Us4 = (const float4*)Us;
    const float4 ub4 = __ldg((const float4*)(ub) + cg);
    float4 acc0 = ub4, acc1 = ub4, acc2 = ub4, acc3 = ub4;
    #pragma unroll 2
    for (int k0 = 0; k0 < 64; k0 += 4) {
        float4 hA = *(const float4*)(hs + rl * 64 + k0);
        float4 hB = *(const float4*)(hs + (rl + 25) * 64 + k0);
        float4 hC = *(const float4*)(hs + (rl + 50) * 64 + k0);
        float4 hD = *(const float4*)(hs + (rl + 75) * 64 + k0);
        float4 u0 = Us4[(k0 + 0) * 16 + cg];
        float4 u1 = Us4[(k0 + 1) * 16 + cg];
        float4 u2 = Us4[(k0 + 2) * 16 + cg];
        float4 u3 = Us4[(k0 + 3) * 16 + cg];
        FMA4(acc0, hA.x, u0) FMA4(acc0, hA.y, u1) FMA4(acc0, hA.z, u2) FMA4(acc0, hA.w, u3)
        FMA4(acc1, hB.x, u0) FMA4(acc1, hB.y, u1) FMA4(acc1, hB.z, u2) FMA4(acc1, hB.w, u3)
        FMA4(acc2, hC.x, u0) FMA4(acc2, hC.y, u1) FMA4(acc2, hC.z, u2) FMA4(acc2, hC.w, u3)
        FMA4(acc3, hD.x, u0) FMA4(acc3, hD.y, u1) FMA4(acc3, hD.z, u2) FMA4(acc3, hD.w, u3)
    }
    #pragma unroll
    for (int jj = 0; jj < 4; jj++) {
        float4 accv = jj == 0 ? acc0 : jj == 1 ? acc1 : jj == 2 ? acc2 : acc3;
        int row = rl + 25 * jj;
        float4 xo = ((float4*)xs)[row * 16 + cg];
        float4 xn = add4(xo, silu4(accv));
        *(float4*)(g_x + (size_t)(node0 + row) * 64 + cg * 4) = xn;
        ((float4*)xs)[row * 16 + cg] = xn;
    }
    __syncthreads();
    const float4* Wa4 = (const float4*)Wab;
    const float4* Wb4 = Wa4 + 1024;
    float4 a0 = make_float4(0, 0, 0, 0), a1 = a0, a2 = a0, a3 = a0;
    float4 b0 = a0, b1 = a0, b2 = a0, b3 = a0;
    #pragma unroll 2
    for (int k0 = 0; k0 < 64; k0 += 2) {
        float2 xA = *(const float2*)(xs + rl * 64 + k0);
        float2 xB = *(const float2*)(xs + (rl + 25) * 64 + k0);
        float2 xC = *(const float2*)(xs + (rl + 50) * 64 + k0);
        float2 xD = *(const float2*)(xs + (rl + 75) * 64 + k0);
        float4 ua0 = Wa4[k0 * 16 + cg], ua1 = Wa4[(k0 + 1) * 16 + cg];
        float4 ub0 = Wb4[k0 * 16 + cg], ub1 = Wb4[(k0 + 1) * 16 + cg];
        FMA4(a0, xA.x, ua0) FMA4(a0, xA.y, ua1)
        FMA4(b0, xA.x, ub0) FMA4(b0, xA.y, ub1)
        FMA4(a1, xB.x, ua0) FMA4(a1, xB.y, ua1)
        FMA4(b1, xB.x, ub0) FMA4(b1, xB.y, ub1)
        FMA4(a2, xC.x, ua0) FMA4(a2, xC.y, ua1)
        FMA4(b2, xC.x, ub0) FMA4(b2, xC.y, ub1)
        FMA4(a3, xD.x, ua0) FMA4(a3, xD.y, ua1)
        FMA4(b3, xD.x, ub0) FMA4(b3, xD.y, ub1)
    }
    #pragma unroll
    for (int jj = 0; jj < 4; jj++) {
        float4 av = jj == 0 ? a0 : jj == 1 ? a1 : jj == 2 ? a2 : a3;
        float4 bv = jj == 0 ? b0 : jj == 1 ? b1 : jj == 2 ? b2 : b3;
        int node = node0 + rl + 25 * jj;
        *(float4*)(g_a + (size_t)node * 64 + cg * 4) = av;
        *(float4*)(g_b + (size_t)node * 64 + cg * 4) = bv;
    }
}

// ====================== fused update(3) + output head ======================
// dyn smem: U[4096] | xs[6400] | hs[6400] | Wos[192]
__global__ __launch_bounds__(400, 2) void k_update_out(
    const float* __restrict__ U, const float* __restrict__ ub,
    const float* __restrict__ Wo, const float* __restrict__ bo,
    float* __restrict__ out) {
    extern __shared__ float smem[];
    float* Us  = smem;
    float* xs  = smem + 4096;
    float* hs  = xs + 6400;
    float* Wos = hs + 6400;
    const int tid = threadIdx.x;
    const int node0 = blockIdx.x * 100;
    {
        float4* d = (float4*)Us; const float4* s = (const float4*)U;
        for (int i = tid; i < 1024; i += 400) d[i] = s[i];
        if (tid < 192) Wos[tid] = Wo[tid];
    }
    for (int i = tid; i < 1600; i += 400) {
        int row = i >> 4, c4 = i & 15;
        float4 xv = *(const float4*)(g_x   + (size_t)(node0 + row) * 64 + c4 * 4);
        float4 av = *(const float4*)(g_acc + (size_t)(node0 + row) * 64 + c4 * 4);
        ((float4*)xs)[i] = xv;
        ((float4*)hs)[i] = make_float4(xv.x + 0.25f * av.x, xv.y + 0.25f * av.y,
                                       xv.z + 0.25f * av.z, xv.w + 0.25f * av.w);
    }
    __syncthreads();
    const int rl = tid >> 4, cg = tid & 15;
    const float4* Us4 = (const float4*)Us;
    const float4 ub4 = __ldg((const float4*)(ub) + cg);
    float4 acc0 = ub4, acc1 = ub4, acc2 = ub4, acc3 = ub4;
    #pragma unroll 2
    for (int k0 = 0; k0 < 64; k0 += 4) {
        float4 hA = *(const float4*)(hs + rl * 64 + k0);
        float4 hB = *(const float4*)(hs + (rl + 25) * 64 + k0);
        float4 hC = *(const float4*)(hs + (rl + 50) * 64 + k0);
        float4 hD = *(const float4*)(hs + (rl + 75) * 64 + k0);
        float4 u0 = Us4[(k0 + 0) * 16 + cg];
        float4 u1 = Us4[(k0 + 1) * 16 + cg];
        float4 u2 = Us4[(k0 + 2) * 16 + cg];
        float4 u3 = Us4[(k0 + 3) * 16 + cg];
        FMA4(acc0, hA.x, u0) FMA4(acc0, hA.y, u1) FMA4(acc0, hA.z, u2) FMA4(acc0, hA.w, u3)
        FMA4(acc1, hB.x, u0) FMA4(acc1, hB.y, u1) FMA4(acc1, hB.z, u2) FMA4(acc1, hB.w, u3)
        FMA4(acc2, hC.x, u0) FMA4(acc2, hC.y, u1) FMA4(acc2, hC.z, u2) FMA4(acc2, hC.w, u3)
        FMA4(acc3, hD.x, u0) FMA4(acc3, hD.y, u1) FMA4(acc3, hD.z, u2) FMA4(acc3, hD.w, u3)
    }
    #pragma unroll
    for (int jj = 0; jj < 4; jj++) {
        float4 accv = jj == 0 ? acc0 : jj == 1 ? acc1 : jj == 2 ? acc2 : acc3;
        int row = rl + 25 * jj;
        int node = node0 + row;
        float4 sv = silu4(accv);
        float4 xo = ((float4*)xs)[row * 16 + cg];
        float4 x0v = *(const float4*)(g_x0 + (size_t)node * 64 + cg * 4);
        float4 v = make_float4(x0v.x + xo.x + sv.x, x0v.y + xo.y + sv.y,
                               x0v.z + xo.z + sv.z, x0v.w + xo.w + sv.w);
        const int cb = cg * 4;
        float p0 = v.x * Wos[(cb + 0) * 3 + 0] + v.y * Wos[(cb + 1) * 3 + 0]
                 + v.z * Wos[(cb + 2) * 3 + 0] + v.w * Wos[(cb + 3) * 3 + 0];
        float p1 = v.x * Wos[(cb + 0) * 3 + 1] + v.y * Wos[(cb + 1) * 3 + 1]
                 + v.z * Wos[(cb + 2) * 3 + 1] + v.w * Wos[(cb + 3) * 3 + 1];
        float p2 = v.x * Wos[(cb + 0) * 3 + 2] + v.y * Wos[(cb + 1) * 3 + 2]
                 + v.z * Wos[(cb + 2) * 3 + 2] + v.w * Wos[(cb + 3) * 3 + 2];
        #pragma unroll
        for (int off = 8; off > 0; off >>= 1) {
            p0 += __shfl_down_sync(0xFFFFFFFFu, p0, off, 16);
            p1 += __shfl_down_sync(0xFFFFFFFFu, p1, off, 16);
            p2 += __shfl_down_sync(0xFFFFFFFFu, p2, off, 16);
        }
        if (cg == 0) {
            out[node * 3 + 0] = p0 + __ldg(bo + 0);
            out[node * 3 + 1] = p1 + __ldg(bo + 1);
            out[node * 3 + 2] = p2 + __ldg(bo + 2);
        }
    }
}

// ================================ launcher =================================
extern "C" void kernel_launch(void* const* d_in, const int* in_sizes, int n_in,
                              void* d_out, int out_size) {
    const float* oh   = (const float*)d_in[0];
    const float* pos  = (const float*)d_in[1];
    const int*   ei   = (const int*)d_in[2];
    const float* embW = (const float*)d_in[3];
    const float* embB = (const float*)d_in[4];
    const float* iW   = (const float*)d_in[5];   // [4, 128, 64]
    const float* iB   = (const float*)d_in[6];   // [4, 64]
    const float* uW   = (const float*)d_in[7];   // [4, 64, 64]
    const float* uB   = (const float*)d_in[8];   // [4, 64]
    const float* oW   = (const float*)d_in[9];   // [64, 3]
    const float* oB   = (const float*)d_in[10];  // [3]
    float* out = (float*)d_out;

    static cudaStream_t s2 = nullptr;
    static cudaEvent_t ev_fork = nullptr, ev_join = nullptr;
    static bool attrs_set = false;
    const int EMBED_SMEM  = (7936 + 9920 + 5120) * 4;          // 91,904 B
    const int UPDATE_SMEM = (4096 + 8192 + 6400 + 6400) * 4;   // 100,352 B
    const int UOUT_SMEM   = (4096 + 6400 + 6400 + 192) * 4;    // 68,352 B
    if (!attrs_set) {
        cudaStreamCreateWithFlags(&s2, cudaStreamNonBlocking);
        cudaEventCreateWithFlags(&ev_fork, cudaEventDisableTiming);
        cudaEventCreateWithFlags(&ev_join, cudaEventDisableTiming);
        cudaFuncSetAttribute(k_embed_ab,  cudaFuncAttributeMaxDynamicSharedMemorySize, EMBED_SMEM);
        cudaFuncSetAttribute(k_update_ab, cudaFuncAttributeMaxDynamicSharedMemorySize, UPDATE_SMEM);
        cudaFuncSetAttribute(k_update_out,cudaFuncAttributeMaxDynamicSharedMemorySize, UOUT_SMEM);
        attrs_set = true;
    }

    // Fork: CSR build on s2, embed on legacy stream, join before first edge.
    cudaEventRecord(ev_fork, 0);
    cudaStreamWaitEvent(s2, ev_fork, 0);
    k_hist<<<(N_EDGES / 4 + 255) / 256, 256, 0, s2>>>(ei);
    k_scan<<<1, 1024, 0, s2>>>();
    k_scatter<<<(N_EDGES / 4 + 255) / 256, 256, 0, s2>>>(ei);
    cudaEventRecord(ev_join, s2);

    k_embed_ab<<<N_NODES / 80, 320, EMBED_SMEM>>>(oh, pos, embW, embB, iW);
    cudaStreamWaitEvent(0, ev_join, 0);

    for (int l = 0; l < 4; l++) {
        k_edge<<<(N_NODES + 31) / 32, 512>>>(iB + l * 64);
        if (l < 3)
            k_update_ab<<<N_NODES / 100, 400, UPDATE_SMEM>>>(
                uW + (size_t)l * 4096, uB + l * 64, iW + (size_t)(l + 1) * 8192);
        else
            k_update_out<<<N_NODES / 100, 400, UOUT_SMEM>>>(
                uW + (size_t)l * 4096, uB + l * 64, oW, oB, out);
    }
}

// round 15
// speedup vs baseline: 1.3579x; 1.0055x over previous
#include <cuda_runtime.h>
#include <cuda_fp16.h>
#include <cstdint>

#define N_NODES 50000
#define N_EDGES 800000
#define H 64

// ---------------- scratch (device globals; no allocations) ----------------
__device__ __align__(16) float g_x0 [N_NODES * H];
__device__ __align__(16) float g_x  [N_NODES * H];
__device__ __align__(16) float g_a  [N_NODES * H];
__device__ __align__(16) __half g_hb[N_NODES * H];   // gathered operand in fp16
__device__ __align__(16) float g_acc[N_NODES * H];
__device__ __align__(16) int g_deg[N_NODES];     // static-zero; re-zeroed by k_scan
__device__ int g_off[N_NODES + 1];
__device__ int g_cursor[N_NODES];
__device__ int g_csr[N_EDGES];

// silu(z) = 0.5*z*(1 + tanh(z/2)) -- single MUFU.TANH
__device__ __forceinline__ float silu_f(float z) {
    float t;
    asm("tanh.approx.f32 %0, %1;" : "=f"(t) : "f"(0.5f * z));
    return 0.5f * z * (1.0f + t);
}
__device__ __forceinline__ float4 silu4(float4 z) {
    return make_float4(silu_f(z.x), silu_f(z.y), silu_f(z.z), silu_f(z.w));
}
__device__ __forceinline__ float4 add4(float4 a, float4 b) {
    return make_float4(a.x + b.x, a.y + b.y, a.z + b.z, a.w + b.w);
}
// fp16 pack/unpack: 4 floats <-> uint2 (4 halves)
__device__ __forceinline__ uint2 f4_to_h4(float4 v) {
    __half2 lo = __floats2half2_rn(v.x, v.y);
    __half2 hi = __floats2half2_rn(v.z, v.w);
    uint2 r;
    r.x = *reinterpret_cast<unsigned*>(&lo);
    r.y = *reinterpret_cast<unsigned*>(&hi);
    return r;
}
__device__ __forceinline__ float4 h4_to_f4(uint2 u) {
    __half2 lo = *reinterpret_cast<__half2*>(&u.x);
    __half2 hi = *reinterpret_cast<__half2*>(&u.y);
    float2 fa = __half22float2(lo), fb = __half22float2(hi);
    return make_float4(fa.x, fa.y, fb.x, fb.y);
}

// A_ (float4) += h_ (scalar) * w_ (float4)   [hygienic param names]
#define FMA4(A_, h_, w_) \
    A_.x = fmaf(h_, w_.x, A_.x); A_.y = fmaf(h_, w_.y, A_.y); \
    A_.z = fmaf(h_, w_.z, A_.z); A_.w = fmaf(h_, w_.w, A_.w);

// ============================ CSR construction =============================
__global__ void k_hist(const int* __restrict__ ei) {
    int i = blockIdx.x * blockDim.x + threadIdx.x;
    if (i < N_EDGES / 4) {
        int4 v = ((const int4*)ei)[i];
        atomicAdd(&g_deg[v.x], 1);
        atomicAdd(&g_deg[v.y], 1);
        atomicAdd(&g_deg[v.z], 1);
        atomicAdd(&g_deg[v.w], 1);
    }
}

__global__ __launch_bounds__(1024) void k_scan() {
    __shared__ int wsum[32];
    __shared__ int s_carry;
    const int tid = threadIdx.x, lane = tid & 31, w = tid >> 5;
    if (tid == 0) { g_off[0] = 0; s_carry = 0; }
    __syncthreads();
    const int NI4 = N_NODES / 4;  // 12500
    for (int base = 0; base < NI4; base += 1024) {
        int i4 = base + tid;
        int4 v = make_int4(0, 0, 0, 0);
        if (i4 < NI4) {
            v = ((const int4*)g_deg)[i4];
            ((int4*)g_deg)[i4] = make_int4(0, 0, 0, 0);   // re-zero for next call
        }
        int s0 = v.x, s1 = s0 + v.y, s2 = s1 + v.z, s3 = s2 + v.w;
        int x = s3;
        #pragma unroll
        for (int o = 1; o < 32; o <<= 1) {
            int t = __shfl_up_sync(0xFFFFFFFFu, x, o);
            if (lane >= o) x += t;
        }
        if (lane == 31) wsum[w] = x;
        __syncthreads();
        if (w == 0) {
            int ws = wsum[lane];
            #pragma unroll
            for (int o = 1; o < 32; o <<= 1) {
                int t = __shfl_up_sync(0xFFFFFFFFu, ws, o);
                if (lane >= o) ws += t;
            }
            wsum[lane] = ws;
        }
        __syncthreads();
        int c = s_carry;
        int ex = (x - s3) + (w ? wsum[w - 1] : 0) + c;
        int tile_total = wsum[31];
        if (i4 < NI4) {
            int o = i4 * 4;
            g_off[o + 1] = ex + s0;  g_off[o + 2] = ex + s1;
            g_off[o + 3] = ex + s2;  g_off[o + 4] = ex + s3;
            g_cursor[o] = ex;            g_cursor[o + 1] = ex + s0;
            g_cursor[o + 2] = ex + s1;   g_cursor[o + 3] = ex + s2;
        }
        __syncthreads();
        if (tid == 0) s_carry = c + tile_total;
        __syncthreads();
    }
}

__global__ void k_scatter(const int* __restrict__ ei) {
    int i = blockIdx.x * blockDim.x + threadIdx.x;
    if (i < N_EDGES / 4) {
        int4 s = ((const int4*)ei)[i];
        int4 d = ((const int4*)(ei + N_EDGES))[i];
        int p0 = atomicAdd(&g_cursor[s.x], 1);
        int p1 = atomicAdd(&g_cursor[s.y], 1);
        int p2 = atomicAdd(&g_cursor[s.z], 1);
        int p3 = atomicAdd(&g_cursor[s.w], 1);
        g_csr[p0] = d.x; g_csr[p1] = d.y; g_csr[p2] = d.z; g_csr[p3] = d.w;
    }
}

// ====================== fused embed + interact-GEMM(0) =====================
// 80 nodes/block, 320 threads (20 groups x 16); thread = 4 rows x 4 cols.
__global__ __launch_bounds__(320, 2) void k_embed_ab(
    const float* __restrict__ oh, const float* __restrict__ pos,
    const float* __restrict__ embW, const float* __restrict__ embB,
    const float* __restrict__ Wab0) {
    extern __shared__ float smem[];
    float* Ws  = smem;            // 7936 (rows 121-123 zeroed)
    float* buf = smem + 7936;     // 9920 union region
    float* xs  = smem + 17856;    // 5120
    const int tid = threadIdx.x;
    const int node0 = blockIdx.x * 80;
    {
        float4* d = (float4*)Ws; const float4* s = (const float4*)embW;
        for (int i = tid; i < 1936; i += 320) d[i] = s[i];
        for (int i = tid; i < 48; i += 320) d[1936 + i] = make_float4(0, 0, 0, 0);
    }
    float* in_s = buf;
    for (int i = tid; i < 80 * 118; i += 320) {
        int row = i / 118, k = i % 118;
        in_s[row * 124 + k] = oh[(size_t)(node0 + row) * 118 + k];
    }
    for (int i = tid; i < 80 * 3; i += 320) {
        int row = i / 3, k = i % 3;
        in_s[row * 124 + 118 + k] = pos[(size_t)(node0 + row) * 3 + k];
        in_s[row * 124 + 121 + k] = 0.0f;
    }
    __syncthreads();
    const int g = tid >> 4, cg = tid & 15;
    const float4* Ws4 = (const float4*)Ws;
    const float4 eb4 = __ldg((const float4*)(embB) + cg);
    float4 A0 = eb4, A1 = eb4, A2 = eb4, A3 = eb4;
    #pragma unroll 2
    for (int k0 = 0; k0 < 124; k0 += 4) {
        float4 hA = *(const float4*)(in_s + g * 124 + k0);
        float4 hB = *(const float4*)(in_s + (g + 20) * 124 + k0);
        float4 hC = *(const float4*)(in_s + (g + 40) * 124 + k0);
        float4 hD = *(const float4*)(in_s + (g + 60) * 124 + k0);
        float4 u0 = Ws4[(k0 + 0) * 16 + cg];
        float4 u1 = Ws4[(k0 + 1) * 16 + cg];
        float4 u2 = Ws4[(k0 + 2) * 16 + cg];
        float4 u3 = Ws4[(k0 + 3) * 16 + cg];
        FMA4(A0, hA.x, u0) FMA4(A0, hA.y, u1) FMA4(A0, hA.z, u2) FMA4(A0, hA.w, u3)
        FMA4(A1, hB.x, u0) FMA4(A1, hB.y, u1) FMA4(A1, hB.z, u2) FMA4(A1, hB.w, u3)
        FMA4(A2, hC.x, u0) FMA4(A2, hC.y, u1) FMA4(A2, hC.z, u2) FMA4(A2, hC.w, u3)
        FMA4(A3, hD.x, u0) FMA4(A3, hD.y, u1) FMA4(A3, hD.z, u2) FMA4(A3, hD.w, u3)
    }
    #pragma unroll
    for (int jj = 0; jj < 4; jj++) {
        float4 av = jj == 0 ? A0 : jj == 1 ? A1 : jj == 2 ? A2 : A3;
        int row = g + 20 * jj;
        int node = node0 + row;
        float4 xv = silu4(av);
        *(float4*)(g_x0 + (size_t)node * 64 + cg * 4) = xv;
        *(float4*)(g_x  + (size_t)node * 64 + cg * 4) = xv;
        ((float4*)xs)[row * 16 + cg] = xv;
    }
    __syncthreads();
    {
        float4* d = (float4*)buf; const float4* s = (const float4*)Wab0;
        for (int i = tid; i < 2048; i += 320) d[i] = s[i];
    }
    __syncthreads();
    const float4* Wa4 = (const float4*)buf;
    const float4* Wb4 = Wa4 + 1024;
    float4 a0 = make_float4(0, 0, 0, 0), a1 = a0, a2 = a0, a3 = a0;
    float4 b0 = a0, b1 = a0, b2 = a0, b3 = a0;
    #pragma unroll 2
    for (int k0 = 0; k0 < 64; k0 += 2) {
        float2 xA = *(const float2*)(xs + g * 64 + k0);
        float2 xB = *(const float2*)(xs + (g + 20) * 64 + k0);
        float2 xC = *(const float2*)(xs + (g + 40) * 64 + k0);
        float2 xD = *(const float2*)(xs + (g + 60) * 64 + k0);
        float4 ua0 = Wa4[k0 * 16 + cg], ua1 = Wa4[(k0 + 1) * 16 + cg];
        float4 ub0 = Wb4[k0 * 16 + cg], ub1 = Wb4[(k0 + 1) * 16 + cg];
        FMA4(a0, xA.x, ua0) FMA4(a0, xA.y, ua1)
        FMA4(b0, xA.x, ub0) FMA4(b0, xA.y, ub1)
        FMA4(a1, xB.x, ua0) FMA4(a1, xB.y, ua1)
        FMA4(b1, xB.x, ub0) FMA4(b1, xB.y, ub1)
        FMA4(a2, xC.x, ua0) FMA4(a2, xC.y, ua1)
        FMA4(b2, xC.x, ub0) FMA4(b2, xC.y, ub1)
        FMA4(a3, xD.x, ua0) FMA4(a3, xD.y, ua1)
        FMA4(b3, xD.x, ub0) FMA4(b3, xD.y, ub1)
    }
    #pragma unroll
    for (int jj = 0; jj < 4; jj++) {
        float4 av = jj == 0 ? a0 : jj == 1 ? a1 : jj == 2 ? a2 : a3;
        float4 bv = jj == 0 ? b0 : jj == 1 ? b1 : jj == 2 ? b2 : b3;
        int node = node0 + g + 20 * jj;
        *(float4*)(g_a + (size_t)node * 64 + cg * 4) = av;
        *(uint2*)(g_hb + (size_t)node * 64 + cg * 4) = f4_to_h4(bv);
    }
}

// ========================== CSR edge aggregation ===========================
// b gathered as fp16 (8 B per thread per edge instead of 16 B)
__global__ __launch_bounds__(512) void k_edge(const float* __restrict__ bias) {
    const int tid = threadIdx.x;
    const int s = blockIdx.x * 32 + (tid >> 4);
    if (s >= N_NODES) return;
    const int c4 = tid & 15;
    float4 a4 = *(const float4*)(g_a + (size_t)s * 64 + c4 * 4);
    a4 = add4(a4, __ldg((const float4*)bias + c4));
    int j = g_off[s];
    const int end = g_off[s + 1];
    float4 acc = make_float4(0, 0, 0, 0);
    for (; j + 3 < end; j += 4) {
        int d0 = __ldg(g_csr + j);
        int d1 = __ldg(g_csr + j + 1);
        int d2 = __ldg(g_csr + j + 2);
        int d3 = __ldg(g_csr + j + 3);
        uint2 h0 = __ldg((const uint2*)(g_hb + (size_t)d0 * 64 + c4 * 4));
        uint2 h1 = __ldg((const uint2*)(g_hb + (size_t)d1 * 64 + c4 * 4));
        uint2 h2 = __ldg((const uint2*)(g_hb + (size_t)d2 * 64 + c4 * 4));
        uint2 h3 = __ldg((const uint2*)(g_hb + (size_t)d3 * 64 + c4 * 4));
        acc = add4(acc, silu4(add4(a4, h4_to_f4(h0))));
        acc = add4(acc, silu4(add4(a4, h4_to_f4(h1))));
        acc = add4(acc, silu4(add4(a4, h4_to_f4(h2))));
        acc = add4(acc, silu4(add4(a4, h4_to_f4(h3))));
    }
    for (; j < end; ++j) {
        int d = __ldg(g_csr + j);
        uint2 h0 = __ldg((const uint2*)(g_hb + (size_t)d * 64 + c4 * 4));
        acc = add4(acc, silu4(add4(a4, h4_to_f4(h0))));
    }
    *(float4*)(g_acc + (size_t)s * 64 + c4 * 4) = acc;
}

// =================== fused update(l) + interact-GEMM(l+1) ==================
__global__ __launch_bounds__(400, 2) void k_update_ab(
    const float* __restrict__ U, const float* __restrict__ ub,
    const float* __restrict__ Wabn) {
    extern __shared__ float smem[];
    float* Us  = smem;
    float* Wab = smem + 4096;
    float* xs  = smem + 4096 + 8192;
    float* hs  = xs + 6400;
    const int tid = threadIdx.x;
    const int node0 = blockIdx.x * 100;
    {
        float4* d = (float4*)Us; const float4* s = (const float4*)U;
        for (int i = tid; i < 1024; i += 400) d[i] = s[i];
        float4* d2 = (float4*)Wab; const float4* s2 = (const float4*)Wabn;
        for (int i = tid; i < 2048; i += 400) d2[i] = s2[i];
    }
    for (int i = tid; i < 1600; i += 400) {
        int row = i >> 4, c4 = i & 15;
        float4 xv = *(const float4*)(g_x   + (size_t)(node0 + row) * 64 + c4 * 4);
        float4 av = *(const float4*)(g_acc + (size_t)(node0 + row) * 64 + c4 * 4);
        ((float4*)xs)[i] = xv;
        ((float4*)hs)[i] = make_float4(xv.x + 0.25f * av.x, xv.y + 0.25f * av.y,
                                       xv.z + 0.25f * av.z, xv.w + 0.25f * av.w);
    }
    __syncthreads();
    const int rl = tid >> 4, cg = tid & 15;
    const float4* Us4 = (const float4*)Us;
    const float4 ub4 = __ldg((const float4*)(ub) + cg);
    float4 acc0 = ub4, acc1 = ub4, acc2 = ub4, acc3 = ub4;
    #pragma unroll 2
    for (int k0 = 0; k0 < 64; k0 += 4) {
        float4 hA = *(const float4*)(hs + rl * 64 + k0);
        float4 hB = *(const float4*)(hs + (rl + 25) * 64 + k0);
        float4 hC = *(const float4*)(hs + (rl + 50) * 64 + k0);
        float4 hD = *(const float4*)(hs + (rl + 75) * 64 + k0);
        float4 u0 = Us4[(k0 + 0) * 16 + cg];
        float4 u1 = Us4[(k0 + 1) * 16 + cg];
        float4 u2 = Us4[(k0 + 2) * 16 + cg];
        float4 u3 = Us4[(k0 + 3) * 16 + cg];
        FMA4(acc0, hA.x, u0) FMA4(acc0, hA.y, u1) FMA4(acc0, hA.z, u2) FMA4(acc0, hA.w, u3)
        FMA4(acc1, hB.x, u0) FMA4(acc1, hB.y, u1) FMA4(acc1, hB.z, u2) FMA4(acc1, hB.w, u3)
        FMA4(acc2, hC.x, u0) FMA4(acc2, hC.y, u1) FMA4(acc2, hC.z, u2) FMA4(acc2, hC.w, u3)
        FMA4(acc3, hD.x, u0) FMA4(acc3, hD.y, u1) FMA4(acc3, hD.z, u2) FMA4(acc3, hD.w, u3)
    }
    #pragma unroll
    for (int jj = 0; jj < 4; jj++) {
        float4 accv = jj == 0 ? acc0 : jj == 1 ? acc1 : jj == 2 ? acc2 : acc3;
        int row = rl + 25 * jj;
        float4 xo = ((float4*)xs)[row * 16 + cg];
        float4 xn = add4(xo, silu4(accv));
        *(float4*)(g_x + (size_t)(node0 + row) * 64 + cg * 4) = xn;
        ((float4*)xs)[row * 16 + cg] = xn;
    }
    __syncthreads();
    const float4* Wa4 = (const float4*)Wab;
    const float4* Wb4 = Wa4 + 1024;
    float4 a0 = make_float4(0, 0, 0, 0), a1 = a0, a2 = a0, a3 = a0;
    float4 b0 = a0, b1 = a0, b2 = a0, b3 = a0;
    #pragma unroll 2
    for (int k0 = 0; k0 < 64; k0 += 2) {
        float2 xA = *(const float2*)(xs + rl * 64 + k0);
        float2 xB = *(const float2*)(xs + (rl + 25) * 64 + k0);
        float2 xC = *(const float2*)(xs + (rl + 50) * 64 + k0);
        float2 xD = *(const float2*)(xs + (rl + 75) * 64 + k0);
        float4 ua0 = Wa4[k0 * 16 + cg], ua1 = Wa4[(k0 + 1) * 16 + cg];
        float4 ub0 = Wb4[k0 * 16 + cg], ub1 = Wb4[(k0 + 1) * 16 + cg];
        FMA4(a0, xA.x, ua0) FMA4(a0, xA.y, ua1)
        FMA4(b0, xA.x, ub0) FMA4(b0, xA.y, ub1)
        FMA4(a1, xB.x, ua0) FMA4(a1, xB.y, ua1)
        FMA4(b1, xB.x, ub0) FMA4(b1, xB.y, ub1)
        FMA4(a2, xC.x, ua0) FMA4(a2, xC.y, ua1)
        FMA4(b2, xC.x, ub0) FMA4(b2, xC.y, ub1)
        FMA4(a3, xD.x, ua0) FMA4(a3, xD.y, ua1)
        FMA4(b3, xD.x, ub0) FMA4(b3, xD.y, ub1)
    }
    #pragma unroll
    for (int jj = 0; jj < 4; jj++) {
        float4 av = jj == 0 ? a0 : jj == 1 ? a1 : jj == 2 ? a2 : a3;
        float4 bv = jj == 0 ? b0 : jj == 1 ? b1 : jj == 2 ? b2 : b3;
        int node = node0 + rl + 25 * jj;
        *(float4*)(g_a + (size_t)node * 64 + cg * 4) = av;
        *(uint2*)(g_hb + (size_t)node * 64 + cg * 4) = f4_to_h4(bv);
    }
}

// ====================== fused update(3) + output head ======================
__global__ __launch_bounds__(400, 2) void k_update_out(
    const float* __restrict__ U, const float* __restrict__ ub,
    const float* __restrict__ Wo, const float* __restrict__ bo,
    float* __restrict__ out) {
    extern __shared__ float smem[];
    float* Us  = smem;
    float* xs  = smem + 4096;
    float* hs  = xs + 6400;
    float* Wos = hs + 6400;
    const int tid = threadIdx.x;
    const int node0 = blockIdx.x * 100;
    {
        float4* d = (float4*)Us; const float4* s = (const float4*)U;
        for (int i = tid; i < 1024; i += 400) d[i] = s[i];
        if (tid < 192) Wos[tid] = Wo[tid];
    }
    for (int i = tid; i < 1600; i += 400) {
        int row = i >> 4, c4 = i & 15;
        float4 xv = *(const float4*)(g_x   + (size_t)(node0 + row) * 64 + c4 * 4);
        float4 av = *(const float4*)(g_acc + (size_t)(node0 + row) * 64 + c4 * 4);
        ((float4*)xs)[i] = xv;
        ((float4*)hs)[i] = make_float4(xv.x + 0.25f * av.x, xv.y + 0.25f * av.y,
                                       xv.z + 0.25f * av.z, xv.w + 0.25f * av.w);
    }
    __syncthreads();
    const int rl = tid >> 4, cg = tid & 15;
    const float4* Us4 = (const float4*)Us;
    const float4 ub4 = __ldg((const float4*)(ub) + cg);
    float4 acc0 = ub4, acc1 = ub4, acc2 = ub4, acc3 = ub4;
    #pragma unroll 2
    for (int k0 = 0; k0 < 64; k0 += 4) {
        float4 hA = *(const float4*)(hs + rl * 64 + k0);
        float4 hB = *(const float4*)(hs + (rl + 25) * 64 + k0);
        float4 hC = *(const float4*)(hs + (rl + 50) * 64 + k0);
        float4 hD = *(const float4*)(hs + (rl + 75) * 64 + k0);
        float4 u0 = Us4[(k0 + 0) * 16 + cg];
        float4 u1 = Us4[(k0 + 1) * 16 + cg];
        float4 u2 = Us4[(k0 + 2) * 16 + cg];
        float4 u3 = Us4[(k0 + 3) * 16 + cg];
        FMA4(acc0, hA.x, u0) FMA4(acc0, hA.y, u1) FMA4(acc0, hA.z, u2) FMA4(acc0, hA.w, u3)
        FMA4(acc1, hB.x, u0) FMA4(acc1, hB.y, u1) FMA4(acc1, hB.z, u2) FMA4(acc1, hB.w, u3)
        FMA4(acc2, hC.x, u0) FMA4(acc2, hC.y, u1) FMA4(acc2, hC.z, u2) FMA4(acc2, hC.w, u3)
        FMA4(acc3, hD.x, u0) FMA4(acc3, hD.y, u1) FMA4(acc3, hD.z, u2) FMA4(acc3, hD.w, u3)
    }
    #pragma unroll
    for (int jj = 0; jj < 4; jj++) {
        float4 accv = jj == 0 ? acc0 : jj == 1 ? acc1 : jj == 2 ? acc2 : acc3;
        int row = rl + 25 * jj;
        int node = node0 + row;
        float4 sv = silu4(accv);
        float4 xo = ((float4*)xs)[row * 16 + cg];
        float4 x0v = *(const float4*)(g_x0 + (size_t)node * 64 + cg * 4);
        float4 v = make_float4(x0v.x + xo.x + sv.x, x0v.y + xo.y + sv.y,
                               x0v.z + xo.z + sv.z, x0v.w + xo.w + sv.w);
        const int cb = cg * 4;
        float p0 = v.x * Wos[(cb + 0) * 3 + 0] + v.y * Wos[(cb + 1) * 3 + 0]
                 + v.z * Wos[(cb + 2) * 3 + 0] + v.w * Wos[(cb + 3) * 3 + 0];
        float p1 = v.x * Wos[(cb + 0) * 3 + 1] + v.y * Wos[(cb + 1) * 3 + 1]
                 + v.z * Wos[(cb + 2) * 3 + 1] + v.w * Wos[(cb + 3) * 3 + 1];
        float p2 = v.x * Wos[(cb + 0) * 3 + 2] + v.y * Wos[(cb + 1) * 3 + 2]
                 + v.z * Wos[(cb + 2) * 3 + 2] + v.w * Wos[(cb + 3) * 3 + 2];
        #pragma unroll
        for (int off = 8; off > 0; off >>= 1) {
            p0 += __shfl_down_sync(0xFFFFFFFFu, p0, off, 16);
            p1 += __shfl_down_sync(0xFFFFFFFFu, p1, off, 16);
            p2 += __shfl_down_sync(0xFFFFFFFFu, p2, off, 16);
        }
        if (cg == 0) {
            out[node * 3 + 0] = p0 + __ldg(bo + 0);
            out[node * 3 + 1] = p1 + __ldg(bo + 1);
            out[node * 3 + 2] = p2 + __ldg(bo + 2);
        }
    }
}

// ================================ launcher =================================
extern "C" void kernel_launch(void* const* d_in, const int* in_sizes, int n_in,
                              void* d_out, int out_size) {
    const float* oh   = (const float*)d_in[0];
    const float* pos  = (const float*)d_in[1];
    const int*   ei   = (const int*)d_in[2];
    const float* embW = (const float*)d_in[3];
    const float* embB = (const float*)d_in[4];
    const float* iW   = (const float*)d_in[5];   // [4, 128, 64]
    const float* iB   = (const float*)d_in[6];   // [4, 64]
    const float* uW   = (const float*)d_in[7];   // [4, 64, 64]
    const float* uB   = (const float*)d_in[8];   // [4, 64]
    const float* oW   = (const float*)d_in[9];   // [64, 3]
    const float* oB   = (const float*)d_in[10];  // [3]
    float* out = (float*)d_out;

    static cudaStream_t s2 = nullptr;
    static cudaEvent_t ev_fork = nullptr, ev_join = nullptr;
    static bool attrs_set = false;
    const int EMBED_SMEM  = (7936 + 9920 + 5120) * 4;          // 91,904 B
    const int UPDATE_SMEM = (4096 + 8192 + 6400 + 6400) * 4;   // 100,352 B
    const int UOUT_SMEM   = (4096 + 6400 + 6400 + 192) * 4;    // 68,352 B
    if (!attrs_set) {
        cudaStreamCreateWithFlags(&s2, cudaStreamNonBlocking);
        cudaEventCreateWithFlags(&ev_fork, cudaEventDisableTiming);
        cudaEventCreateWithFlags(&ev_join, cudaEventDisableTiming);
        cudaFuncSetAttribute(k_embed_ab,  cudaFuncAttributeMaxDynamicSharedMemorySize, EMBED_SMEM);
        cudaFuncSetAttribute(k_update_ab, cudaFuncAttributeMaxDynamicSharedMemorySize, UPDATE_SMEM);
        cudaFuncSetAttribute(k_update_out,cudaFuncAttributeMaxDynamicSharedMemorySize, UOUT_SMEM);
        attrs_set = true;
    }

    // Fork: CSR build on s2, embed on legacy stream, join before first edge.
    cudaEventRecord(ev_fork, 0);
    cudaStreamWaitEvent(s2, ev_fork, 0);
    k_hist<<<(N_EDGES / 4 + 255) / 256, 256, 0, s2>>>(ei);
    k_scan<<<1, 1024, 0, s2>>>();
    k_scatter<<<(N_EDGES / 4 + 255) / 256, 256, 0, s2>>>(ei);
    cudaEventRecord(ev_join, s2);

    k_embed_ab<<<N_NODES / 80, 320, EMBED_SMEM>>>(oh, pos, embW, embB, iW);
    cudaStreamWaitEvent(0, ev_join, 0);

    for (int l = 0; l < 4; l++) {
        k_edge<<<(N_NODES + 31) / 32, 512>>>(iB + l * 64);
        if (l < 3)
            k_update_ab<<<N_NODES / 100, 400, UPDATE_SMEM>>>(
                uW + (size_t)l * 4096, uB + l * 64, iW + (size_t)(l + 1) * 8192);
        else
            k_update_out<<<N_NODES / 100, 400, UOUT_SMEM>>>(
                uW + (size_t)l * 4096, uB + l * 64, oW, oB, out);
    }
}